// round 1
// baseline (speedup 1.0000x reference)
#include <cuda_runtime.h>
#include <math.h>

// Problem constants
#define CC 512
#define TT 2048
#define BBATCH 2
#define HH 8
#define DD 64
#define LLAYERS 6
#define VV 32000
#define NROW (BBATCH*TT)   // 4096

// ---------------- scratch (no allocations allowed) ----------------
__device__ float g_x  [NROW * CC];        // residual stream
__device__ float g_xn [NROW * CC];        // layernorm output
__device__ float g_qkv[NROW * 3 * CC];    // qkv projections
__device__ float g_att[NROW * CC];        // attention output (pre out-proj)
__device__ float g_ff [NROW * 4 * CC];    // ff hidden
__device__ float g_nll[NROW];             // per-token nll

// ---------------- embedding ----------------
__global__ void embed_k(const int* __restrict__ idx,
                        const float* __restrict__ tok,
                        const float* __restrict__ pos,
                        float* __restrict__ x) {
    int row = blockIdx.x;            // 0..4095  (b*T + t)
    int t   = row & (TT - 1);
    int tokid = idx[row];
    const float4* te = (const float4*)(tok + (size_t)tokid * CC);
    const float4* pe = (const float4*)(pos + (size_t)t * CC);
    float4* xr = (float4*)(x + (size_t)row * CC);
    for (int i = threadIdx.x; i < CC / 4; i += blockDim.x) {
        float4 a = te[i], b = pe[i];
        a.x += b.x; a.y += b.y; a.z += b.z; a.w += b.w;
        xr[i] = a;
    }
}

// ---------------- layernorm (one block per row, 128 threads) ----------------
__global__ __launch_bounds__(128) void ln_k(const float* __restrict__ x,
                                            const float* __restrict__ w,
                                            const float* __restrict__ b,
                                            float* __restrict__ y) {
    int row = blockIdx.x;
    int tid = threadIdx.x;           // 128 threads, each owns 4 floats
    const float4* xr = (const float4*)(x + (size_t)row * CC);
    float4 v = xr[tid];
    float s = v.x + v.y + v.z + v.w;
    float q = v.x * v.x + v.y * v.y + v.z * v.z + v.w * v.w;
    #pragma unroll
    for (int o = 16; o > 0; o >>= 1) {
        s += __shfl_xor_sync(0xffffffffu, s, o);
        q += __shfl_xor_sync(0xffffffffu, q, o);
    }
    __shared__ float ss[4], qq[4];
    int wid = tid >> 5;
    if ((tid & 31) == 0) { ss[wid] = s; qq[wid] = q; }
    __syncthreads();
    s = ss[0] + ss[1] + ss[2] + ss[3];
    q = qq[0] + qq[1] + qq[2] + qq[3];
    float mu   = s * (1.0f / CC);
    float var  = q * (1.0f / CC) - mu * mu;
    float rstd = rsqrtf(var + 1e-5f);
    float4 wv = ((const float4*)w)[tid];
    float4 bv = ((const float4*)b)[tid];
    float4 o;
    o.x = (v.x - mu) * rstd * wv.x + bv.x;
    o.y = (v.y - mu) * rstd * wv.y + bv.y;
    o.z = (v.z - mu) * rstd * wv.z + bv.z;
    o.w = (v.w - mu) * rstd * wv.w + bv.w;
    ((float4*)(y + (size_t)row * CC))[tid] = o;
}

// ---------------- generic NT SGEMM: C[m,n] = sum_k A[m,k]*B[n,k] + bias[n] ----------------
// 128x128 block tile, BK=8, 256 threads, 8x8 per-thread tile.
// mode: 0 = plain, 1 = exact GELU, 2 = residual add (C = acc + bias + res)
#define MODE_NONE 0
#define MODE_GELU 1
#define MODE_RES  2

__device__ __forceinline__ float gelu_exact(float x) {
    return 0.5f * x * (1.0f + erff(x * 0.70710678118654752f));
}

__global__ __launch_bounds__(256) void gemm_nt(const float* __restrict__ A,
                                               const float* __restrict__ B,
                                               const float* __restrict__ bias,
                                               const float* __restrict__ res,
                                               float* __restrict__ C,
                                               int M, int N, int K, int mode) {
    __shared__ float As[8][128];
    __shared__ float Bs[8][128];
    int tid = threadIdx.x;
    int bm = blockIdx.y * 128;
    int bn = blockIdx.x * 128;
    int ty = tid >> 4;          // 0..15
    int tx = tid & 15;          // 0..15

    float acc[8][8];
    #pragma unroll
    for (int i = 0; i < 8; i++)
        #pragma unroll
        for (int j = 0; j < 8; j++) acc[i][j] = 0.0f;

    int ldRow = tid >> 1;            // 0..127
    int ldC   = (tid & 1) * 4;       // 0 or 4
    const float* Ap = A + (size_t)(bm + ldRow) * K + ldC;
    const float* Bp = B + (size_t)(bn + ldRow) * K + ldC;

    for (int k0 = 0; k0 < K; k0 += 8) {
        float4 av = *(const float4*)(Ap + k0);
        float4 bv = *(const float4*)(Bp + k0);
        As[ldC + 0][ldRow] = av.x;
        As[ldC + 1][ldRow] = av.y;
        As[ldC + 2][ldRow] = av.z;
        As[ldC + 3][ldRow] = av.w;
        Bs[ldC + 0][ldRow] = bv.x;
        Bs[ldC + 1][ldRow] = bv.y;
        Bs[ldC + 2][ldRow] = bv.z;
        Bs[ldC + 3][ldRow] = bv.w;
        __syncthreads();
        #pragma unroll
        for (int kk = 0; kk < 8; kk++) {
            float4 a0 = *(const float4*)&As[kk][ty * 8];
            float4 a1 = *(const float4*)&As[kk][ty * 8 + 4];
            float4 b0 = *(const float4*)&Bs[kk][tx * 8];
            float4 b1 = *(const float4*)&Bs[kk][tx * 8 + 4];
            float ar[8] = {a0.x, a0.y, a0.z, a0.w, a1.x, a1.y, a1.z, a1.w};
            float br[8] = {b0.x, b0.y, b0.z, b0.w, b1.x, b1.y, b1.z, b1.w};
            #pragma unroll
            for (int i = 0; i < 8; i++)
                #pragma unroll
                for (int j = 0; j < 8; j++)
                    acc[i][j] = fmaf(ar[i], br[j], acc[i][j]);
        }
        __syncthreads();
    }

    float bb[8];
    #pragma unroll
    for (int j = 0; j < 8; j++) bb[j] = bias[bn + tx * 8 + j];

    #pragma unroll
    for (int i = 0; i < 8; i++) {
        int m = bm + ty * 8 + i;
        float* cp = C + (size_t)m * N + bn + tx * 8;
        float v[8];
        #pragma unroll
        for (int j = 0; j < 8; j++) v[j] = acc[i][j] + bb[j];
        if (mode == MODE_GELU) {
            #pragma unroll
            for (int j = 0; j < 8; j++) v[j] = gelu_exact(v[j]);
        } else if (mode == MODE_RES) {
            const float* rp = res + (size_t)m * N + bn + tx * 8;
            float4 r0 = *(const float4*)rp;
            float4 r1 = *(const float4*)(rp + 4);
            v[0] += r0.x; v[1] += r0.y; v[2] += r0.z; v[3] += r0.w;
            v[4] += r1.x; v[5] += r1.y; v[6] += r1.z; v[7] += r1.w;
        }
        float4 o0 = make_float4(v[0], v[1], v[2], v[3]);
        float4 o1 = make_float4(v[4], v[5], v[6], v[7]);
        *(float4*)cp = o0;
        *(float4*)(cp + 4) = o1;
    }
}

// ---------------- flash attention (causal), one query per thread ----------------
// grid: (T/128, B*H), 128 threads/block. D=64, fp32, online softmax.
__global__ __launch_bounds__(128) void attn_k(const float* __restrict__ qkv,
                                              float* __restrict__ out) {
    int bh = blockIdx.y;
    int b = bh >> 3;
    int h = bh & 7;
    int qi = blockIdx.x * 128 + threadIdx.x;   // query index within batch
    const float* base = qkv + (size_t)b * TT * (3 * CC);

    float q[64];
    {
        const float4* qp = (const float4*)(base + (size_t)qi * (3 * CC) + h * DD);
        #pragma unroll
        for (int i = 0; i < 16; i++) {
            float4 v = qp[i];
            q[4 * i + 0] = v.x * 0.125f;
            q[4 * i + 1] = v.y * 0.125f;
            q[4 * i + 2] = v.z * 0.125f;
            q[4 * i + 3] = v.w * 0.125f;
        }
    }

    float m = -1e30f, l = 0.0f;
    float acc[64];
    #pragma unroll
    for (int d = 0; d < 64; d++) acc[d] = 0.0f;

    __shared__ float Ks[32][64];
    __shared__ float Vs[32][64];

    int lastk  = blockIdx.x * 128 + 127;
    int ntiles = lastk / 32 + 1;

    for (int t = 0; t < ntiles; t++) {
        __syncthreads();
        // stage K and V tiles (32 keys x 64 dims each)
        for (int i = threadIdx.x; i < 512; i += 128) {
            int r = i >> 4;
            int c = (i & 15) << 2;
            int krow = t * 32 + r;
            const float* kp = base + (size_t)krow * (3 * CC) + CC + h * DD + c;
            *(float4*)&Ks[r][c] = *(const float4*)kp;
            *(float4*)&Vs[r][c] = *(const float4*)(kp + CC);
        }
        __syncthreads();

        int jmax = qi - t * 32;
        if (jmax > 31) jmax = 31;
        for (int j = 0; j <= jmax; j++) {
            float s0 = 0.f, s1 = 0.f, s2 = 0.f, s3 = 0.f;
            #pragma unroll
            for (int d4 = 0; d4 < 16; d4++) {
                float4 kv = *(const float4*)&Ks[j][d4 * 4];
                s0 = fmaf(q[d4 * 4 + 0], kv.x, s0);
                s1 = fmaf(q[d4 * 4 + 1], kv.y, s1);
                s2 = fmaf(q[d4 * 4 + 2], kv.z, s2);
                s3 = fmaf(q[d4 * 4 + 3], kv.w, s3);
            }
            float s = (s0 + s1) + (s2 + s3);
            float mn = fmaxf(m, s);
            float cs = __expf(m - mn);
            float p  = __expf(s - mn);
            l = l * cs + p;
            m = mn;
            #pragma unroll
            for (int d4 = 0; d4 < 16; d4++) {
                float4 vv = *(const float4*)&Vs[j][d4 * 4];
                acc[d4 * 4 + 0] = fmaf(acc[d4 * 4 + 0], cs, p * vv.x);
                acc[d4 * 4 + 1] = fmaf(acc[d4 * 4 + 1], cs, p * vv.y);
                acc[d4 * 4 + 2] = fmaf(acc[d4 * 4 + 2], cs, p * vv.z);
                acc[d4 * 4 + 3] = fmaf(acc[d4 * 4 + 3], cs, p * vv.w);
            }
        }
    }

    float inv = 1.0f / l;
    float* op = out + (size_t)(b * TT + qi) * CC + h * DD;
    #pragma unroll
    for (int i = 0; i < 16; i++) {
        float4 o = make_float4(acc[4*i]*inv, acc[4*i+1]*inv, acc[4*i+2]*inv, acc[4*i+3]*inv);
        ((float4*)op)[i] = o;
    }
}

// ---------------- per-row logsumexp + NLL ----------------
__global__ __launch_bounds__(256) void nll_k(const float* __restrict__ logits,
                                             const int* __restrict__ tgt,
                                             float* __restrict__ nll) {
    int row = blockIdx.x;
    const float* lp = logits + (size_t)row * VV;
    float m = -1e30f, s = 0.0f;
    for (int j = threadIdx.x; j < VV; j += 256) {
        float v = lp[j];
        float mn = fmaxf(m, v);
        s = s * __expf(m - mn) + __expf(v - mn);
        m = mn;
    }
    #pragma unroll
    for (int o = 16; o > 0; o >>= 1) {
        float m2 = __shfl_xor_sync(0xffffffffu, m, o);
        float s2 = __shfl_xor_sync(0xffffffffu, s, o);
        float mn = fmaxf(m, m2);
        s = s * __expf(m - mn) + s2 * __expf(m2 - mn);
        m = mn;
    }
    __shared__ float ms[8], ls[8];
    int wid = threadIdx.x >> 5;
    if ((threadIdx.x & 31) == 0) { ms[wid] = m; ls[wid] = s; }
    __syncthreads();
    if (threadIdx.x == 0) {
        float M = ms[0], S = ls[0];
        #pragma unroll
        for (int w = 1; w < 8; w++) {
            float mn = fmaxf(M, ms[w]);
            S = S * __expf(M - mn) + ls[w] * __expf(ms[w] - mn);
            M = mn;
        }
        float lse = M + logf(S);
        nll[row] = lse - lp[tgt[row]];
    }
}

__global__ __launch_bounds__(256) void loss_k(const float* __restrict__ nll,
                                              float* __restrict__ out_loss) {
    float s = 0.0f;
    for (int i = threadIdx.x; i < NROW; i += 256) s += nll[i];
    #pragma unroll
    for (int o = 16; o > 0; o >>= 1) s += __shfl_xor_sync(0xffffffffu, s, o);
    __shared__ float ws[8];
    int wid = threadIdx.x >> 5;
    if ((threadIdx.x & 31) == 0) ws[wid] = s;
    __syncthreads();
    if (threadIdx.x == 0) {
        float t = 0.0f;
        #pragma unroll
        for (int w = 0; w < 8; w++) t += ws[w];
        out_loss[0] = t / (float)NROW;
    }
}

// ---------------- orchestration ----------------
extern "C" void kernel_launch(void* const* d_in, const int* in_sizes, int n_in,
                              void* d_out, int out_size) {
    const int*   idx       = (const int*)  d_in[0];
    const int*   targets   = (const int*)  d_in[1];
    const float* tok_embed = (const float*)d_in[2];
    const float* pos_embed = (const float*)d_in[3];
    const float* qkv_w     = (const float*)d_in[4];
    const float* qkv_b     = (const float*)d_in[5];
    const float* out_w     = (const float*)d_in[6];
    const float* out_b     = (const float*)d_in[7];
    const float* ln1_w     = (const float*)d_in[8];
    const float* ln1_b     = (const float*)d_in[9];
    const float* ff1_w     = (const float*)d_in[10];
    const float* ff1_b     = (const float*)d_in[11];
    const float* ff2_w     = (const float*)d_in[12];
    const float* ff2_b     = (const float*)d_in[13];
    const float* ln2_w     = (const float*)d_in[14];
    const float* ln2_b     = (const float*)d_in[15];
    const float* lnf_w     = (const float*)d_in[16];
    const float* lnf_b     = (const float*)d_in[17];
    const float* head_w    = (const float*)d_in[18];
    const float* head_b    = (const float*)d_in[19];
    float* logits = (float*)d_out;

    static float *px = nullptr, *pxn = nullptr, *pqkv = nullptr,
                 *patt = nullptr, *pff = nullptr, *pnll = nullptr;
    if (!px) {
        cudaGetSymbolAddress((void**)&px,   g_x);
        cudaGetSymbolAddress((void**)&pxn,  g_xn);
        cudaGetSymbolAddress((void**)&pqkv, g_qkv);
        cudaGetSymbolAddress((void**)&patt, g_att);
        cudaGetSymbolAddress((void**)&pff,  g_ff);
        cudaGetSymbolAddress((void**)&pnll, g_nll);
    }

    embed_k<<<NROW, 128>>>(idx, tok_embed, pos_embed, px);

    dim3 gQKV(3 * CC / 128, NROW / 128);   // (12, 32)
    dim3 gPROJ(CC / 128, NROW / 128);      // (4, 32)
    dim3 gFF1(4 * CC / 128, NROW / 128);   // (16, 32)
    dim3 gHEAD(VV / 128, NROW / 128);      // (250, 32)
    dim3 gATT(TT / 128, BBATCH * HH);      // (16, 16)

    for (int l = 0; l < LLAYERS; l++) {
        ln_k<<<NROW, 128>>>(px, ln1_w + l * CC, ln1_b + l * CC, pxn);
        gemm_nt<<<gQKV, 256>>>(pxn, qkv_w + (size_t)l * 3 * CC * CC,
                               qkv_b + (size_t)l * 3 * CC, nullptr,
                               pqkv, NROW, 3 * CC, CC, MODE_NONE);
        attn_k<<<gATT, 128>>>(pqkv, patt);
        gemm_nt<<<gPROJ, 256>>>(patt, out_w + (size_t)l * CC * CC,
                                out_b + (size_t)l * CC, px,
                                px, NROW, CC, CC, MODE_RES);
        ln_k<<<NROW, 128>>>(px, ln2_w + l * CC, ln2_b + l * CC, pxn);
        gemm_nt<<<gFF1, 256>>>(pxn, ff1_w + (size_t)l * 4 * CC * CC,
                               ff1_b + (size_t)l * 4 * CC, nullptr,
                               pff, NROW, 4 * CC, CC, MODE_GELU);
        gemm_nt<<<gPROJ, 256>>>(pff, ff2_w + (size_t)l * CC * 4 * CC,
                                ff2_b + (size_t)l * CC, px,
                                px, NROW, CC, 4 * CC, MODE_RES);
    }

    ln_k<<<NROW, 128>>>(px, lnf_w, lnf_b, pxn);
    gemm_nt<<<gHEAD, 256>>>(pxn, head_w, head_b, nullptr,
                            logits, NROW, VV, CC, MODE_NONE);

    nll_k<<<NROW, 256>>>(logits, targets, pnll);
    if (out_size > NROW * VV) {
        loss_k<<<1, 256>>>(pnll, logits + (size_t)NROW * VV);
    }
}

// round 3
// speedup vs baseline: 1.5518x; 1.5518x over previous
#include <cuda_runtime.h>
#include <cuda_bf16.h>
#include <math.h>
#include <stdint.h>

// Problem constants
#define CC 512
#define TT 2048
#define BBATCH 2
#define HH 8
#define DD 64
#define LLAYERS 6
#define VV 32000
#define NROW (BBATCH*TT)   // 4096

// ---------------- scratch (no allocations allowed) ----------------
__device__ float g_x  [NROW * CC];
__device__ float g_xn [NROW * CC];
__device__ float g_qkv[NROW * 3 * CC];
__device__ float g_att[NROW * CC];
__device__ float g_ff [NROW * 4 * CC];
__device__ float g_nll[NROW];

// ================= warp-MMA helpers (baseline ISA, no 'a' features) ===========
__device__ __forceinline__ uint32_t smem_u32(const void* p) {
    uint32_t a;
    asm("{ .reg .u64 t; cvta.to.shared.u64 t, %1; cvt.u32.u64 %0, t; }"
        : "=r"(a) : "l"(p));
    return a;
}

__device__ __forceinline__ void ldsm_x4(uint32_t* r, uint32_t addr) {
    asm volatile("ldmatrix.sync.aligned.m8n8.x4.shared.b16 {%0,%1,%2,%3}, [%4];"
                 : "=r"(r[0]), "=r"(r[1]), "=r"(r[2]), "=r"(r[3]) : "r"(addr));
}
__device__ __forceinline__ void ldsm_x2(uint32_t* r, uint32_t addr) {
    asm volatile("ldmatrix.sync.aligned.m8n8.x2.shared.b16 {%0,%1}, [%2];"
                 : "=r"(r[0]), "=r"(r[1]) : "r"(addr));
}
__device__ __forceinline__ void mma_bf16(float* c, const uint32_t* a, const uint32_t* b) {
    asm volatile("mma.sync.aligned.m16n8k16.row.col.f32.bf16.bf16.f32 "
                 "{%0,%1,%2,%3}, {%4,%5,%6,%7}, {%8,%9}, {%0,%1,%2,%3};"
                 : "+f"(c[0]), "+f"(c[1]), "+f"(c[2]), "+f"(c[3])
                 : "r"(a[0]), "r"(a[1]), "r"(a[2]), "r"(a[3]),
                   "r"(b[0]), "r"(b[1]));
}

// ---------------- embedding ----------------
__global__ void embed_k(const int* __restrict__ idx,
                        const float* __restrict__ tok,
                        const float* __restrict__ pos,
                        float* __restrict__ x) {
    int row = blockIdx.x;
    int t   = row & (TT - 1);
    int tokid = idx[row];
    const float4* te = (const float4*)(tok + (size_t)tokid * CC);
    const float4* pe = (const float4*)(pos + (size_t)t * CC);
    float4* xr = (float4*)(x + (size_t)row * CC);
    for (int i = threadIdx.x; i < CC / 4; i += blockDim.x) {
        float4 a = te[i], b = pe[i];
        a.x += b.x; a.y += b.y; a.z += b.z; a.w += b.w;
        xr[i] = a;
    }
}

// ---------------- layernorm ----------------
__global__ __launch_bounds__(128) void ln_k(const float* __restrict__ x,
                                            const float* __restrict__ w,
                                            const float* __restrict__ b,
                                            float* __restrict__ y) {
    int row = blockIdx.x;
    int tid = threadIdx.x;
    const float4* xr = (const float4*)(x + (size_t)row * CC);
    float4 v = xr[tid];
    float s = v.x + v.y + v.z + v.w;
    float q = v.x * v.x + v.y * v.y + v.z * v.z + v.w * v.w;
    #pragma unroll
    for (int o = 16; o > 0; o >>= 1) {
        s += __shfl_xor_sync(0xffffffffu, s, o);
        q += __shfl_xor_sync(0xffffffffu, q, o);
    }
    __shared__ float ss[4], qq[4];
    int wid = tid >> 5;
    if ((tid & 31) == 0) { ss[wid] = s; qq[wid] = q; }
    __syncthreads();
    s = ss[0] + ss[1] + ss[2] + ss[3];
    q = qq[0] + qq[1] + qq[2] + qq[3];
    float mu   = s * (1.0f / CC);
    float var  = q * (1.0f / CC) - mu * mu;
    float rstd = rsqrtf(var + 1e-5f);
    float4 wv = ((const float4*)w)[tid];
    float4 bv = ((const float4*)b)[tid];
    float4 o;
    o.x = (v.x - mu) * rstd * wv.x + bv.x;
    o.y = (v.y - mu) * rstd * wv.y + bv.y;
    o.z = (v.z - mu) * rstd * wv.z + bv.z;
    o.w = (v.w - mu) * rstd * wv.w + bv.w;
    ((float4*)(y + (size_t)row * CC))[tid] = o;
}

// ================= bf16x3 MMA GEMM: C[m,n] = sum_k A[m,k]*B[n,k] + bias ======
#define MODE_NONE 0
#define MODE_GELU 1
#define MODE_RES  2

#define BM 128
#define BN 128
#define BK 32
#define APITCH 40                    // bf16 elems per smem row (80 B, 16B-mult)
#define TILE_B (128 * APITCH * 2)    // 10240 bytes per tile

__device__ __forceinline__ float gelu_exact(float x) {
    return 0.5f * x * (1.0f + erff(x * 0.70710678118654752f));
}

// convert 8 fp32 -> 8 bf16 hi + 8 bf16 lo (packed as uint4 each)
__device__ __forceinline__ void cvt8(float4 v0, float4 v1, uint4& hi, uint4& lo) {
    float f[8] = {v0.x, v0.y, v0.z, v0.w, v1.x, v1.y, v1.z, v1.w};
    uint32_t h[8], l[8];
    #pragma unroll
    for (int i = 0; i < 8; i++) {
        __nv_bfloat16 hb = __float2bfloat16(f[i]);
        __nv_bfloat16 lb = __float2bfloat16(f[i] - __bfloat162float(hb));
        h[i] = (uint32_t)__bfloat16_as_ushort(hb);
        l[i] = (uint32_t)__bfloat16_as_ushort(lb);
    }
    hi.x = h[0] | (h[1] << 16); hi.y = h[2] | (h[3] << 16);
    hi.z = h[4] | (h[5] << 16); hi.w = h[6] | (h[7] << 16);
    lo.x = l[0] | (l[1] << 16); lo.y = l[2] | (l[3] << 16);
    lo.z = l[4] | (l[5] << 16); lo.w = l[6] | (l[7] << 16);
}

__global__ __launch_bounds__(256) void gemm_mma(const float* __restrict__ A,
                                                const float* __restrict__ B,
                                                const float* __restrict__ bias,
                                                const float* __restrict__ res,
                                                float* __restrict__ C,
                                                int N, int K, int mode) {
    __shared__ __align__(16) char smem[4 * TILE_B];   // Ah, Al, Bh, Bl
    uint32_t sb  = smem_u32(smem);
    uint32_t sAh = sb;
    uint32_t sAl = sb + TILE_B;
    uint32_t sBh = sb + 2 * TILE_B;
    uint32_t sBl = sb + 3 * TILE_B;

    int tid  = threadIdx.x;
    int lane = tid & 31;
    int wid  = tid >> 5;
    int wm   = wid & 1;      // 0..1 -> 64-row slab
    int wn   = wid >> 1;     // 0..3 -> 32-col slab
    int bm   = blockIdx.x * BM;
    int bn   = blockIdx.y * BN;

    // staging map: thread t -> row r = t>>1, col half = (t&1)*16
    int sr = tid >> 1;
    int sc = (tid & 1) * 16;
    const float* Ag = A + (size_t)(bm + sr) * K + sc;
    const float* Bg = B + (size_t)(bn + sr) * K + sc;
    uint32_t stb = (uint32_t)(sr * (APITCH * 2) + sc * 2);   // smem byte offset

    float acc[4][4][4];
    #pragma unroll
    for (int i = 0; i < 4; i++)
        #pragma unroll
        for (int j = 0; j < 4; j++)
            #pragma unroll
            for (int r = 0; r < 4; r++) acc[i][j][r] = 0.0f;

    int nk = K / BK;
    float4 pa0, pa1, pa2, pa3, pb0, pb1, pb2, pb3;
    // prefetch step 0
    pa0 = *(const float4*)(Ag + 0);  pa1 = *(const float4*)(Ag + 4);
    pa2 = *(const float4*)(Ag + 8);  pa3 = *(const float4*)(Ag + 12);
    pb0 = *(const float4*)(Bg + 0);  pb1 = *(const float4*)(Bg + 4);
    pb2 = *(const float4*)(Bg + 8);  pb3 = *(const float4*)(Bg + 12);

    for (int t = 0; t < nk; t++) {
        // convert current regs -> smem
        uint4 hi, lo;
        cvt8(pa0, pa1, hi, lo);
        *(uint4*)(smem + (sAh - sb) + stb)      = hi;
        *(uint4*)(smem + (sAl - sb) + stb)      = lo;
        cvt8(pa2, pa3, hi, lo);
        *(uint4*)(smem + (sAh - sb) + stb + 16) = hi;
        *(uint4*)(smem + (sAl - sb) + stb + 16) = lo;
        cvt8(pb0, pb1, hi, lo);
        *(uint4*)(smem + (sBh - sb) + stb)      = hi;
        *(uint4*)(smem + (sBl - sb) + stb)      = lo;
        cvt8(pb2, pb3, hi, lo);
        *(uint4*)(smem + (sBh - sb) + stb + 16) = hi;
        *(uint4*)(smem + (sBl - sb) + stb + 16) = lo;

        // prefetch next step (overlaps with compute below)
        if (t + 1 < nk) {
            const float* An = Ag + (t + 1) * BK;
            const float* Bn = Bg + (t + 1) * BK;
            pa0 = *(const float4*)(An + 0);  pa1 = *(const float4*)(An + 4);
            pa2 = *(const float4*)(An + 8);  pa3 = *(const float4*)(An + 12);
            pb0 = *(const float4*)(Bn + 0);  pb1 = *(const float4*)(Bn + 4);
            pb2 = *(const float4*)(Bn + 8);  pb3 = *(const float4*)(Bn + 12);
        }
        __syncthreads();

        uint32_t ah[4][4], al[4][4], bh[4][2], bl[4][2];
        #pragma unroll
        for (int kf = 0; kf < 2; kf++) {
            uint32_t kb = kf * 32;
            // A row addr: wm*64 + mf*16 + (lane&15), extra +16B for lanes>=16
            uint32_t arow = (uint32_t)(wm * 64 + (lane & 15));
            uint32_t aoff = arow * 80 + kb + ((lane >> 4) * 16);
            // B row addr: wn*32 + nf*8 + (lane&7), +16B for (lane>>3)&1
            uint32_t brow = (uint32_t)(wn * 32 + (lane & 7));
            uint32_t boff = brow * 80 + kb + (((lane >> 3) & 1) * 16);

            #pragma unroll
            for (int nf = 0; nf < 4; nf++) ldsm_x2(bh[nf], sBh + boff + nf * 8 * 80);
            #pragma unroll
            for (int mf = 0; mf < 4; mf++) ldsm_x4(ah[mf], sAh + aoff + mf * 16 * 80);
            #pragma unroll
            for (int mf = 0; mf < 4; mf++)
                #pragma unroll
                for (int nf = 0; nf < 4; nf++)
                    mma_bf16(acc[mf][nf], ah[mf], bh[nf]);

            #pragma unroll
            for (int mf = 0; mf < 4; mf++) ldsm_x4(al[mf], sAl + aoff + mf * 16 * 80);
            #pragma unroll
            for (int mf = 0; mf < 4; mf++)
                #pragma unroll
                for (int nf = 0; nf < 4; nf++)
                    mma_bf16(acc[mf][nf], al[mf], bh[nf]);

            #pragma unroll
            for (int nf = 0; nf < 4; nf++) ldsm_x2(bl[nf], sBl + boff + nf * 8 * 80);
            #pragma unroll
            for (int mf = 0; mf < 4; mf++)
                #pragma unroll
                for (int nf = 0; nf < 4; nf++)
                    mma_bf16(acc[mf][nf], ah[mf], bl[nf]);
        }
        __syncthreads();
    }

    // epilogue
    #pragma unroll
    for (int mf = 0; mf < 4; mf++) {
        int r0 = bm + wm * 64 + mf * 16 + (lane >> 2);
        #pragma unroll
        for (int nf = 0; nf < 4; nf++) {
            int col = bn + wn * 32 + nf * 8 + (lane & 3) * 2;
            float b0 = bias[col], b1 = bias[col + 1];
            float v0 = acc[mf][nf][0] + b0;
            float v1 = acc[mf][nf][1] + b1;
            float v2 = acc[mf][nf][2] + b0;
            float v3 = acc[mf][nf][3] + b1;
            if (mode == MODE_GELU) {
                v0 = gelu_exact(v0); v1 = gelu_exact(v1);
                v2 = gelu_exact(v2); v3 = gelu_exact(v3);
            } else if (mode == MODE_RES) {
                float2 r0v = *(const float2*)(res + (size_t)r0 * N + col);
                float2 r1v = *(const float2*)(res + (size_t)(r0 + 8) * N + col);
                v0 += r0v.x; v1 += r0v.y; v2 += r1v.x; v3 += r1v.y;
            }
            *(float2*)(C + (size_t)r0 * N + col)       = make_float2(v0, v1);
            *(float2*)(C + (size_t)(r0 + 8) * N + col) = make_float2(v2, v3);
        }
    }
}

// ---------------- flash attention (causal), grouped online softmax ----------------
__global__ __launch_bounds__(128) void attn_k(const float* __restrict__ qkv,
                                              float* __restrict__ out) {
    __shared__ float Ks[40][64];   // rows 32..39 are zero padding
    __shared__ float Vs[40][64];
    int bh = blockIdx.y;
    int b = bh >> 3;
    int h = bh & 7;
    int qi = blockIdx.x * 128 + threadIdx.x;
    const float* base = qkv + (size_t)b * TT * (3 * CC);

    // zero the pad rows once (loads below only touch rows 0..31)
    for (int i = threadIdx.x; i < 8 * 64; i += 128) {
        Ks[32 + (i >> 6)][i & 63] = 0.0f;
        Vs[32 + (i >> 6)][i & 63] = 0.0f;
    }

    float q[64];
    {
        const float4* qp = (const float4*)(base + (size_t)qi * (3 * CC) + h * DD);
        #pragma unroll
        for (int i = 0; i < 16; i++) {
            float4 v = qp[i];
            q[4 * i + 0] = v.x * 0.125f;
            q[4 * i + 1] = v.y * 0.125f;
            q[4 * i + 2] = v.z * 0.125f;
            q[4 * i + 3] = v.w * 0.125f;
        }
    }

    float m = -1e30f, l = 0.0f;
    float acc[64];
    #pragma unroll
    for (int d = 0; d < 64; d++) acc[d] = 0.0f;

    int ntiles = blockIdx.x * 4 + 4;

    for (int t = 0; t < ntiles; t++) {
        __syncthreads();
        for (int i = threadIdx.x; i < 512; i += 128) {
            int r = i >> 4;
            int c = (i & 15) << 2;
            int krow = t * 32 + r;
            const float* kp = base + (size_t)krow * (3 * CC) + CC + h * DD + c;
            *(float4*)&Ks[r][c] = *(const float4*)kp;
            *(float4*)&Vs[r][c] = *(const float4*)(kp + CC);
        }
        __syncthreads();

        int jmax = qi - t * 32;
        if (jmax > 31) jmax = 31;
        for (int j0 = 0; j0 <= jmax; j0 += 8) {
            float s[8];
            #pragma unroll
            for (int jj = 0; jj < 8; jj++) {
                const float* kr = Ks[j0 + jj];
                float a0 = 0.f, a1 = 0.f, a2 = 0.f, a3 = 0.f;
                #pragma unroll
                for (int d4 = 0; d4 < 16; d4++) {
                    float4 kv = *(const float4*)(kr + d4 * 4);
                    a0 = fmaf(q[d4 * 4 + 0], kv.x, a0);
                    a1 = fmaf(q[d4 * 4 + 1], kv.y, a1);
                    a2 = fmaf(q[d4 * 4 + 2], kv.z, a2);
                    a3 = fmaf(q[d4 * 4 + 3], kv.w, a3);
                }
                s[jj] = (a0 + a1) + (a2 + a3);
            }
            int lim = jmax - j0;
            #pragma unroll
            for (int jj = 0; jj < 8; jj++)
                if (jj > lim) s[jj] = -1e30f;

            float gm = s[0];
            #pragma unroll
            for (int jj = 1; jj < 8; jj++) gm = fmaxf(gm, s[jj]);
            float mn = fmaxf(m, gm);
            float cs = __expf(m - mn);
            float p[8];
            float ps = 0.f;
            #pragma unroll
            for (int jj = 0; jj < 8; jj++) {
                p[jj] = __expf(s[jj] - mn);
                ps += p[jj];
            }
            l = l * cs + ps;
            m = mn;
            #pragma unroll
            for (int d4 = 0; d4 < 16; d4++) {
                float tx = 0.f, ty = 0.f, tz = 0.f, tw = 0.f;
                #pragma unroll
                for (int jj = 0; jj < 8; jj++) {
                    float4 v = *(const float4*)(Vs[j0 + jj] + d4 * 4);
                    tx = fmaf(p[jj], v.x, tx);
                    ty = fmaf(p[jj], v.y, ty);
                    tz = fmaf(p[jj], v.z, tz);
                    tw = fmaf(p[jj], v.w, tw);
                }
                acc[d4 * 4 + 0] = fmaf(acc[d4 * 4 + 0], cs, tx);
                acc[d4 * 4 + 1] = fmaf(acc[d4 * 4 + 1], cs, ty);
                acc[d4 * 4 + 2] = fmaf(acc[d4 * 4 + 2], cs, tz);
                acc[d4 * 4 + 3] = fmaf(acc[d4 * 4 + 3], cs, tw);
            }
        }
    }

    float inv = 1.0f / l;
    float* op = out + (size_t)(b * TT + qi) * CC + h * DD;
    #pragma unroll
    for (int i = 0; i < 16; i++) {
        float4 o = make_float4(acc[4 * i] * inv, acc[4 * i + 1] * inv,
                               acc[4 * i + 2] * inv, acc[4 * i + 3] * inv);
        ((float4*)op)[i] = o;
    }
}

// ---------------- per-row logsumexp + NLL ----------------
__global__ __launch_bounds__(256) void nll_k(const float* __restrict__ logits,
                                             const int* __restrict__ tgt,
                                             float* __restrict__ nll) {
    int row = blockIdx.x;
    const float* lp = logits + (size_t)row * VV;
    float m = -1e30f, s = 0.0f;
    for (int j = threadIdx.x; j < VV; j += 256) {
        float v = lp[j];
        float mn = fmaxf(m, v);
        s = s * __expf(m - mn) + __expf(v - mn);
        m = mn;
    }
    #pragma unroll
    for (int o = 16; o > 0; o >>= 1) {
        float m2 = __shfl_xor_sync(0xffffffffu, m, o);
        float s2 = __shfl_xor_sync(0xffffffffu, s, o);
        float mn = fmaxf(m, m2);
        s = s * __expf(m - mn) + s2 * __expf(m2 - mn);
        m = mn;
    }
    __shared__ float ms[8], ls[8];
    int wid = threadIdx.x >> 5;
    if ((threadIdx.x & 31) == 0) { ms[wid] = m; ls[wid] = s; }
    __syncthreads();
    if (threadIdx.x == 0) {
        float M = ms[0], S = ls[0];
        #pragma unroll
        for (int w = 1; w < 8; w++) {
            float mn = fmaxf(M, ms[w]);
            S = S * __expf(M - mn) + ls[w] * __expf(ms[w] - mn);
            M = mn;
        }
        float lse = M + logf(S);
        nll[row] = lse - lp[tgt[row]];
    }
}

__global__ __launch_bounds__(256) void loss_k(const float* __restrict__ nll,
                                              float* __restrict__ out_loss) {
    float s = 0.0f;
    for (int i = threadIdx.x; i < NROW; i += 256) s += nll[i];
    #pragma unroll
    for (int o = 16; o > 0; o >>= 1) s += __shfl_xor_sync(0xffffffffu, s, o);
    __shared__ float ws[8];
    int wid = threadIdx.x >> 5;
    if ((threadIdx.x & 31) == 0) ws[wid] = s;
    __syncthreads();
    if (threadIdx.x == 0) {
        float t = 0.0f;
        #pragma unroll
        for (int w = 0; w < 8; w++) t += ws[w];
        out_loss[0] = t / (float)NROW;
    }
}

// ---------------- orchestration ----------------
extern "C" void kernel_launch(void* const* d_in, const int* in_sizes, int n_in,
                              void* d_out, int out_size) {
    const int*   idx       = (const int*)  d_in[0];
    const int*   targets   = (const int*)  d_in[1];
    const float* tok_embed = (const float*)d_in[2];
    const float* pos_embed = (const float*)d_in[3];
    const float* qkv_w     = (const float*)d_in[4];
    const float* qkv_b     = (const float*)d_in[5];
    const float* out_w     = (const float*)d_in[6];
    const float* out_b     = (const float*)d_in[7];
    const float* ln1_w     = (const float*)d_in[8];
    const float* ln1_b     = (const float*)d_in[9];
    const float* ff1_w     = (const float*)d_in[10];
    const float* ff1_b     = (const float*)d_in[11];
    const float* ff2_w     = (const float*)d_in[12];
    const float* ff2_b     = (const float*)d_in[13];
    const float* ln2_w     = (const float*)d_in[14];
    const float* ln2_b     = (const float*)d_in[15];
    const float* lnf_w     = (const float*)d_in[16];
    const float* lnf_b     = (const float*)d_in[17];
    const float* head_w    = (const float*)d_in[18];
    const float* head_b    = (const float*)d_in[19];
    float* logits = (float*)d_out;

    static float *px = nullptr, *pxn = nullptr, *pqkv = nullptr,
                 *patt = nullptr, *pff = nullptr, *pnll = nullptr;
    if (!px) {
        cudaGetSymbolAddress((void**)&px,   g_x);
        cudaGetSymbolAddress((void**)&pxn,  g_xn);
        cudaGetSymbolAddress((void**)&pqkv, g_qkv);
        cudaGetSymbolAddress((void**)&patt, g_att);
        cudaGetSymbolAddress((void**)&pff,  g_ff);
        cudaGetSymbolAddress((void**)&pnll, g_nll);
    }

    embed_k<<<NROW, 128>>>(idx, tok_embed, pos_embed, px);

    dim3 gQKV(NROW / 128, 3 * CC / 128);   // (32, 12)
    dim3 gPROJ(NROW / 128, CC / 128);      // (32, 4)
    dim3 gFF1(NROW / 128, 4 * CC / 128);   // (32, 16)
    dim3 gHEAD(NROW / 128, VV / 128);      // (32, 250)
    dim3 gATT(TT / 128, BBATCH * HH);      // (16, 16)

    for (int l = 0; l < LLAYERS; l++) {
        ln_k<<<NROW, 128>>>(px, ln1_w + l * CC, ln1_b + l * CC, pxn);
        gemm_mma<<<gQKV, 256>>>(pxn, qkv_w + (size_t)l * 3 * CC * CC,
                                qkv_b + (size_t)l * 3 * CC, nullptr,
                                pqkv, 3 * CC, CC, MODE_NONE);
        attn_k<<<gATT, 128>>>(pqkv, patt);
        gemm_mma<<<gPROJ, 256>>>(patt, out_w + (size_t)l * CC * CC,
                                 out_b + (size_t)l * CC, px,
                                 px, CC, CC, MODE_RES);
        ln_k<<<NROW, 128>>>(px, ln2_w + l * CC, ln2_b + l * CC, pxn);
        gemm_mma<<<gFF1, 256>>>(pxn, ff1_w + (size_t)l * 4 * CC * CC,
                                ff1_b + (size_t)l * 4 * CC, nullptr,
                                pff, 4 * CC, CC, MODE_GELU);
        gemm_mma<<<gPROJ, 256>>>(pff, ff2_w + (size_t)l * CC * 4 * CC,
                                 ff2_b + (size_t)l * CC, px,
                                 px, CC, 4 * CC, MODE_RES);
    }

    ln_k<<<NROW, 128>>>(px, lnf_w, lnf_b, pxn);
    gemm_mma<<<gHEAD, 256>>>(pxn, head_w, head_b, nullptr,
                             logits, VV, CC, MODE_NONE);

    nll_k<<<NROW, 256>>>(logits, targets, pnll);
    if (out_size > NROW * VV) {
        loss_k<<<1, 256>>>(pnll, logits + (size_t)NROW * VV);
    }
}

// round 4
// speedup vs baseline: 2.5033x; 1.6132x over previous
#include <cuda_runtime.h>
#include <cuda_bf16.h>
#include <math.h>
#include <stdint.h>

// Problem constants
#define CC 512
#define TT 2048
#define BBATCH 2
#define HH 8
#define DD 64
#define LLAYERS 6
#define VV 32000
#define NROW (BBATCH*TT)   // 4096

// ---------------- scratch (no allocations allowed) ----------------
__device__ float g_x  [NROW * CC];
__device__ float g_xn [NROW * CC];
__device__ float g_qkv[NROW * 3 * CC];
__device__ float g_att[NROW * CC];
__device__ float g_ff [NROW * 4 * CC];
__device__ float g_nll[NROW];

// ================= warp-MMA helpers (baseline ISA, no 'a' features) ===========
__device__ __forceinline__ uint32_t smem_u32(const void* p) {
    uint32_t a;
    asm("{ .reg .u64 t; cvta.to.shared.u64 t, %1; cvt.u32.u64 %0, t; }"
        : "=r"(a) : "l"(p));
    return a;
}

__device__ __forceinline__ void ldsm_x4(uint32_t* r, uint32_t addr) {
    asm volatile("ldmatrix.sync.aligned.m8n8.x4.shared.b16 {%0,%1,%2,%3}, [%4];"
                 : "=r"(r[0]), "=r"(r[1]), "=r"(r[2]), "=r"(r[3]) : "r"(addr));
}
__device__ __forceinline__ void ldsm_x2(uint32_t* r, uint32_t addr) {
    asm volatile("ldmatrix.sync.aligned.m8n8.x2.shared.b16 {%0,%1}, [%2];"
                 : "=r"(r[0]), "=r"(r[1]) : "r"(addr));
}
__device__ __forceinline__ void ldsm_x2_t(uint32_t* r, uint32_t addr) {
    asm volatile("ldmatrix.sync.aligned.m8n8.x2.trans.shared.b16 {%0,%1}, [%2];"
                 : "=r"(r[0]), "=r"(r[1]) : "r"(addr));
}
__device__ __forceinline__ void mma_bf16(float* c, const uint32_t* a, const uint32_t* b) {
    asm volatile("mma.sync.aligned.m16n8k16.row.col.f32.bf16.bf16.f32 "
                 "{%0,%1,%2,%3}, {%4,%5,%6,%7}, {%8,%9}, {%0,%1,%2,%3};"
                 : "+f"(c[0]), "+f"(c[1]), "+f"(c[2]), "+f"(c[3])
                 : "r"(a[0]), "r"(a[1]), "r"(a[2]), "r"(a[3]),
                   "r"(b[0]), "r"(b[1]));
}

// split two fp32 into packed bf16 hi pair + lo pair
__device__ __forceinline__ void split2(float a, float b, uint32_t& hi, uint32_t& lo) {
    __nv_bfloat16 ha = __float2bfloat16(a), hb = __float2bfloat16(b);
    __nv_bfloat16 la = __float2bfloat16(a - __bfloat162float(ha));
    __nv_bfloat16 lb = __float2bfloat16(b - __bfloat162float(hb));
    hi = (uint32_t)__bfloat16_as_ushort(ha) | ((uint32_t)__bfloat16_as_ushort(hb) << 16);
    lo = (uint32_t)__bfloat16_as_ushort(la) | ((uint32_t)__bfloat16_as_ushort(lb) << 16);
}

// ---------------- embedding ----------------
__global__ void embed_k(const int* __restrict__ idx,
                        const float* __restrict__ tok,
                        const float* __restrict__ pos,
                        float* __restrict__ x) {
    int row = blockIdx.x;
    int t   = row & (TT - 1);
    int tokid = idx[row];
    const float4* te = (const float4*)(tok + (size_t)tokid * CC);
    const float4* pe = (const float4*)(pos + (size_t)t * CC);
    float4* xr = (float4*)(x + (size_t)row * CC);
    for (int i = threadIdx.x; i < CC / 4; i += blockDim.x) {
        float4 a = te[i], b = pe[i];
        a.x += b.x; a.y += b.y; a.z += b.z; a.w += b.w;
        xr[i] = a;
    }
}

// ---------------- layernorm ----------------
__global__ __launch_bounds__(128) void ln_k(const float* __restrict__ x,
                                            const float* __restrict__ w,
                                            const float* __restrict__ b,
                                            float* __restrict__ y) {
    int row = blockIdx.x;
    int tid = threadIdx.x;
    const float4* xr = (const float4*)(x + (size_t)row * CC);
    float4 v = xr[tid];
    float s = v.x + v.y + v.z + v.w;
    float q = v.x * v.x + v.y * v.y + v.z * v.z + v.w * v.w;
    #pragma unroll
    for (int o = 16; o > 0; o >>= 1) {
        s += __shfl_xor_sync(0xffffffffu, s, o);
        q += __shfl_xor_sync(0xffffffffu, q, o);
    }
    __shared__ float ss[4], qq[4];
    int wid = tid >> 5;
    if ((tid & 31) == 0) { ss[wid] = s; qq[wid] = q; }
    __syncthreads();
    s = ss[0] + ss[1] + ss[2] + ss[3];
    q = qq[0] + qq[1] + qq[2] + qq[3];
    float mu   = s * (1.0f / CC);
    float var  = q * (1.0f / CC) - mu * mu;
    float rstd = rsqrtf(var + 1e-5f);
    float4 wv = ((const float4*)w)[tid];
    float4 bv = ((const float4*)b)[tid];
    float4 o;
    o.x = (v.x - mu) * rstd * wv.x + bv.x;
    o.y = (v.y - mu) * rstd * wv.y + bv.y;
    o.z = (v.z - mu) * rstd * wv.z + bv.z;
    o.w = (v.w - mu) * rstd * wv.w + bv.w;
    ((float4*)(y + (size_t)row * CC))[tid] = o;
}

// ================= bf16x3 MMA GEMM (unchanged from R3) ======
#define MODE_NONE 0
#define MODE_GELU 1
#define MODE_RES  2

#define BM 128
#define BN 128
#define BK 32
#define APITCH 40
#define TILE_B (128 * APITCH * 2)

__device__ __forceinline__ float gelu_exact(float x) {
    return 0.5f * x * (1.0f + erff(x * 0.70710678118654752f));
}

__device__ __forceinline__ void cvt8(float4 v0, float4 v1, uint4& hi, uint4& lo) {
    float f[8] = {v0.x, v0.y, v0.z, v0.w, v1.x, v1.y, v1.z, v1.w};
    uint32_t h[8], l[8];
    #pragma unroll
    for (int i = 0; i < 8; i++) {
        __nv_bfloat16 hb = __float2bfloat16(f[i]);
        __nv_bfloat16 lb = __float2bfloat16(f[i] - __bfloat162float(hb));
        h[i] = (uint32_t)__bfloat16_as_ushort(hb);
        l[i] = (uint32_t)__bfloat16_as_ushort(lb);
    }
    hi.x = h[0] | (h[1] << 16); hi.y = h[2] | (h[3] << 16);
    hi.z = h[4] | (h[5] << 16); hi.w = h[6] | (h[7] << 16);
    lo.x = l[0] | (l[1] << 16); lo.y = l[2] | (l[3] << 16);
    lo.z = l[4] | (l[5] << 16); lo.w = l[6] | (l[7] << 16);
}

__global__ __launch_bounds__(256) void gemm_mma(const float* __restrict__ A,
                                                const float* __restrict__ B,
                                                const float* __restrict__ bias,
                                                const float* __restrict__ res,
                                                float* __restrict__ C,
                                                int N, int K, int mode) {
    __shared__ __align__(16) char smem[4 * TILE_B];
    uint32_t sb  = smem_u32(smem);
    uint32_t sAh = sb;
    uint32_t sAl = sb + TILE_B;
    uint32_t sBh = sb + 2 * TILE_B;
    uint32_t sBl = sb + 3 * TILE_B;

    int tid  = threadIdx.x;
    int lane = tid & 31;
    int wid  = tid >> 5;
    int wm   = wid & 1;
    int wn   = wid >> 1;
    int bm   = blockIdx.x * BM;
    int bn   = blockIdx.y * BN;

    int sr = tid >> 1;
    int sc = (tid & 1) * 16;
    const float* Ag = A + (size_t)(bm + sr) * K + sc;
    const float* Bg = B + (size_t)(bn + sr) * K + sc;
    uint32_t stb = (uint32_t)(sr * (APITCH * 2) + sc * 2);

    float acc[4][4][4];
    #pragma unroll
    for (int i = 0; i < 4; i++)
        #pragma unroll
        for (int j = 0; j < 4; j++)
            #pragma unroll
            for (int r = 0; r < 4; r++) acc[i][j][r] = 0.0f;

    int nk = K / BK;
    float4 pa0, pa1, pa2, pa3, pb0, pb1, pb2, pb3;
    pa0 = *(const float4*)(Ag + 0);  pa1 = *(const float4*)(Ag + 4);
    pa2 = *(const float4*)(Ag + 8);  pa3 = *(const float4*)(Ag + 12);
    pb0 = *(const float4*)(Bg + 0);  pb1 = *(const float4*)(Bg + 4);
    pb2 = *(const float4*)(Bg + 8);  pb3 = *(const float4*)(Bg + 12);

    for (int t = 0; t < nk; t++) {
        uint4 hi, lo;
        cvt8(pa0, pa1, hi, lo);
        *(uint4*)(smem + (sAh - sb) + stb)      = hi;
        *(uint4*)(smem + (sAl - sb) + stb)      = lo;
        cvt8(pa2, pa3, hi, lo);
        *(uint4*)(smem + (sAh - sb) + stb + 16) = hi;
        *(uint4*)(smem + (sAl - sb) + stb + 16) = lo;
        cvt8(pb0, pb1, hi, lo);
        *(uint4*)(smem + (sBh - sb) + stb)      = hi;
        *(uint4*)(smem + (sBl - sb) + stb)      = lo;
        cvt8(pb2, pb3, hi, lo);
        *(uint4*)(smem + (sBh - sb) + stb + 16) = hi;
        *(uint4*)(smem + (sBl - sb) + stb + 16) = lo;

        if (t + 1 < nk) {
            const float* An = Ag + (t + 1) * BK;
            const float* Bn = Bg + (t + 1) * BK;
            pa0 = *(const float4*)(An + 0);  pa1 = *(const float4*)(An + 4);
            pa2 = *(const float4*)(An + 8);  pa3 = *(const float4*)(An + 12);
            pb0 = *(const float4*)(Bn + 0);  pb1 = *(const float4*)(Bn + 4);
            pb2 = *(const float4*)(Bn + 8);  pb3 = *(const float4*)(Bn + 12);
        }
        __syncthreads();

        uint32_t ah[4][4], al[4][4], bh[4][2], bl[4][2];
        #pragma unroll
        for (int kf = 0; kf < 2; kf++) {
            uint32_t kb = kf * 32;
            uint32_t arow = (uint32_t)(wm * 64 + (lane & 15));
            uint32_t aoff = arow * 80 + kb + ((lane >> 4) * 16);
            uint32_t brow = (uint32_t)(wn * 32 + (lane & 7));
            uint32_t boff = brow * 80 + kb + (((lane >> 3) & 1) * 16);

            #pragma unroll
            for (int nf = 0; nf < 4; nf++) ldsm_x2(bh[nf], sBh + boff + nf * 8 * 80);
            #pragma unroll
            for (int mf = 0; mf < 4; mf++) ldsm_x4(ah[mf], sAh + aoff + mf * 16 * 80);
            #pragma unroll
            for (int mf = 0; mf < 4; mf++)
                #pragma unroll
                for (int nf = 0; nf < 4; nf++)
                    mma_bf16(acc[mf][nf], ah[mf], bh[nf]);

            #pragma unroll
            for (int mf = 0; mf < 4; mf++) ldsm_x4(al[mf], sAl + aoff + mf * 16 * 80);
            #pragma unroll
            for (int mf = 0; mf < 4; mf++)
                #pragma unroll
                for (int nf = 0; nf < 4; nf++)
                    mma_bf16(acc[mf][nf], al[mf], bh[nf]);

            #pragma unroll
            for (int nf = 0; nf < 4; nf++) ldsm_x2(bl[nf], sBl + boff + nf * 8 * 80);
            #pragma unroll
            for (int mf = 0; mf < 4; mf++)
                #pragma unroll
                for (int nf = 0; nf < 4; nf++)
                    mma_bf16(acc[mf][nf], ah[mf], bl[nf]);
        }
        __syncthreads();
    }

    #pragma unroll
    for (int mf = 0; mf < 4; mf++) {
        int r0 = bm + wm * 64 + mf * 16 + (lane >> 2);
        #pragma unroll
        for (int nf = 0; nf < 4; nf++) {
            int col = bn + wn * 32 + nf * 8 + (lane & 3) * 2;
            float b0 = bias[col], b1 = bias[col + 1];
            float v0 = acc[mf][nf][0] + b0;
            float v1 = acc[mf][nf][1] + b1;
            float v2 = acc[mf][nf][2] + b0;
            float v3 = acc[mf][nf][3] + b1;
            if (mode == MODE_GELU) {
                v0 = gelu_exact(v0); v1 = gelu_exact(v1);
                v2 = gelu_exact(v2); v3 = gelu_exact(v3);
            } else if (mode == MODE_RES) {
                float2 r0v = *(const float2*)(res + (size_t)r0 * N + col);
                float2 r1v = *(const float2*)(res + (size_t)(r0 + 8) * N + col);
                v0 += r0v.x; v1 += r0v.y; v2 += r1v.x; v3 += r1v.y;
            }
            *(float2*)(C + (size_t)r0 * N + col)       = make_float2(v0, v1);
            *(float2*)(C + (size_t)(r0 + 8) * N + col) = make_float2(v2, v3);
        }
    }
}

// ================= tensor-core flash attention =================
// block: 128 queries, 8 warps x 16 rows; K-tiles of 64 keys.
// smem layout (bytes), pitch 144 B per 64-col bf16 row:
#define SQH 0
#define SQL 18432
#define SKH 36864
#define SKL 46080
#define SVH 55296
#define SVL 64512
#define ATT_SMEM 73728

__global__ __launch_bounds__(256) void attn_mma(const float* __restrict__ qkv,
                                                float* __restrict__ out) {
    extern __shared__ __align__(16) char sm[];
    uint32_t sb = smem_u32(sm);
    int tid = threadIdx.x, lane = tid & 31, w = tid >> 5;
    int bh = blockIdx.y, b = bh >> 3, h = bh & 7;
    int qb = (int)gridDim.x - 1 - (int)blockIdx.x;   // heavy blocks first
    const float* base = qkv + (size_t)b * TT * (3 * CC);

    // ---- stage Q (scaled by 1/8), hi/lo split ----
    {
        int r = tid >> 1, hf = tid & 1;
        const float* qg = base + (size_t)(qb * 128 + r) * (3 * CC) + h * DD + hf * 32;
        #pragma unroll
        for (int j = 0; j < 8; j++) {
            float4 v = *(const float4*)(qg + j * 4);
            v.x *= 0.125f; v.y *= 0.125f; v.z *= 0.125f; v.w *= 0.125f;
            uint32_t h0, l0u, h1, l1u;
            split2(v.x, v.y, h0, l0u);
            split2(v.z, v.w, h1, l1u);
            uint32_t off = (uint32_t)(r * 144 + hf * 64 + j * 8);
            *(uint2*)(sm + SQH + off) = make_uint2(h0, h1);
            *(uint2*)(sm + SQL + off) = make_uint2(l0u, l1u);
        }
    }
    __syncthreads();

    // Q fragments (held in registers for the whole block)
    uint32_t qh[4][4], qlo[4][4];
    {
        uint32_t ro = (uint32_t)((w * 16 + (lane & 15)) * 144 + ((lane >> 4) * 16));
        #pragma unroll
        for (int kf = 0; kf < 4; kf++) {
            ldsm_x4(qh[kf],  sb + SQH + ro + kf * 32);
            ldsm_x4(qlo[kf], sb + SQL + ro + kf * 32);
        }
    }

    float o[8][4];
    #pragma unroll
    for (int i = 0; i < 8; i++)
        #pragma unroll
        for (int j = 0; j < 4; j++) o[i][j] = 0.0f;
    float m0 = -1e30f, m1 = -1e30f, l0 = 0.0f, l1 = 0.0f;

    int ntiles = qb * 2 + 2;
    int sr2 = tid >> 2, qd = tid & 3;
    const float* kgb = base + CC + h * DD + qd * 16;
    const float* vgb = base + 2 * CC + h * DD + qd * 16;

    float4 kr[4], vr[4];
    #pragma unroll
    for (int j = 0; j < 4; j++) {
        kr[j] = *(const float4*)(kgb + (size_t)sr2 * (3 * CC) + j * 4);
        vr[j] = *(const float4*)(vgb + (size_t)sr2 * (3 * CC) + j * 4);
    }

    for (int t = 0; t < ntiles; t++) {
        __syncthreads();
        // stage K/V tile t (hi/lo bf16)
        #pragma unroll
        for (int j = 0; j < 4; j++) {
            uint32_t h0, l0u, h1, l1u;
            uint32_t off = (uint32_t)(sr2 * 144 + qd * 32 + j * 8);
            split2(kr[j].x, kr[j].y, h0, l0u);
            split2(kr[j].z, kr[j].w, h1, l1u);
            *(uint2*)(sm + SKH + off) = make_uint2(h0, h1);
            *(uint2*)(sm + SKL + off) = make_uint2(l0u, l1u);
            split2(vr[j].x, vr[j].y, h0, l0u);
            split2(vr[j].z, vr[j].w, h1, l1u);
            *(uint2*)(sm + SVH + off) = make_uint2(h0, h1);
            *(uint2*)(sm + SVL + off) = make_uint2(l0u, l1u);
        }
        __syncthreads();

        // prefetch next tile into regs (overlaps MMA phase)
        if (t + 1 < ntiles) {
            size_t roff = (size_t)((t + 1) * 64 + sr2) * (3 * CC);
            #pragma unroll
            for (int j = 0; j < 4; j++) {
                kr[j] = *(const float4*)(kgb + roff + j * 4);
                vr[j] = *(const float4*)(vgb + roff + j * 4);
            }
        }

        // ---- S = Q K^T (3-term bf16 split) ----
        float sacc[8][4];
        #pragma unroll
        for (int i = 0; i < 8; i++)
            #pragma unroll
            for (int j = 0; j < 4; j++) sacc[i][j] = 0.0f;

        #pragma unroll
        for (int kf = 0; kf < 4; kf++) {
            uint32_t kb2[8][2];
            uint32_t bo = (uint32_t)((lane & 7) * 144 + kf * 32 + ((lane >> 3) & 1) * 16);
            #pragma unroll
            for (int nf = 0; nf < 8; nf++) ldsm_x2(kb2[nf], sb + SKH + bo + nf * 8 * 144);
            #pragma unroll
            for (int nf = 0; nf < 8; nf++) mma_bf16(sacc[nf], qh[kf],  kb2[nf]);
            #pragma unroll
            for (int nf = 0; nf < 8; nf++) mma_bf16(sacc[nf], qlo[kf], kb2[nf]);
            #pragma unroll
            for (int nf = 0; nf < 8; nf++) ldsm_x2(kb2[nf], sb + SKL + bo + nf * 8 * 144);
            #pragma unroll
            for (int nf = 0; nf < 8; nf++) mma_bf16(sacc[nf], qh[kf],  kb2[nf]);
        }

        // ---- causal mask (only diagonal block tiles) ----
        if (t >= 2 * qb) {
            int row0 = qb * 128 + w * 16 + (lane >> 2);
            int kc0  = t * 64 + (lane & 3) * 2;
            #pragma unroll
            for (int nf = 0; nf < 8; nf++) {
                int kc = kc0 + nf * 8;
                if (kc     > row0)     sacc[nf][0] = -1e30f;
                if (kc + 1 > row0)     sacc[nf][1] = -1e30f;
                if (kc     > row0 + 8) sacc[nf][2] = -1e30f;
                if (kc + 1 > row0 + 8) sacc[nf][3] = -1e30f;
            }
        }

        // ---- online softmax ----
        float mx0 = -1e30f, mx1 = -1e30f;
        #pragma unroll
        for (int nf = 0; nf < 8; nf++) {
            mx0 = fmaxf(mx0, fmaxf(sacc[nf][0], sacc[nf][1]));
            mx1 = fmaxf(mx1, fmaxf(sacc[nf][2], sacc[nf][3]));
        }
        mx0 = fmaxf(mx0, __shfl_xor_sync(0xffffffffu, mx0, 1));
        mx0 = fmaxf(mx0, __shfl_xor_sync(0xffffffffu, mx0, 2));
        mx1 = fmaxf(mx1, __shfl_xor_sync(0xffffffffu, mx1, 1));
        mx1 = fmaxf(mx1, __shfl_xor_sync(0xffffffffu, mx1, 2));
        float mn0 = fmaxf(m0, mx0), mn1 = fmaxf(m1, mx1);
        float cs0 = __expf(m0 - mn0), cs1 = __expf(m1 - mn1);
        m0 = mn0; m1 = mn1;
        float ps0 = 0.0f, ps1 = 0.0f;
        #pragma unroll
        for (int nf = 0; nf < 8; nf++) {
            sacc[nf][0] = __expf(sacc[nf][0] - m0); ps0 += sacc[nf][0];
            sacc[nf][1] = __expf(sacc[nf][1] - m0); ps0 += sacc[nf][1];
            sacc[nf][2] = __expf(sacc[nf][2] - m1); ps1 += sacc[nf][2];
            sacc[nf][3] = __expf(sacc[nf][3] - m1); ps1 += sacc[nf][3];
        }
        l0 = l0 * cs0 + ps0;
        l1 = l1 * cs1 + ps1;
        #pragma unroll
        for (int nd = 0; nd < 8; nd++) {
            o[nd][0] *= cs0; o[nd][1] *= cs0;
            o[nd][2] *= cs1; o[nd][3] *= cs1;
        }

        // ---- build P fragments (hi/lo) ----
        uint32_t ph[4][4], plo[4][4];
        #pragma unroll
        for (int j = 0; j < 4; j++) {
            split2(sacc[2 * j][0],     sacc[2 * j][1],     ph[j][0], plo[j][0]);
            split2(sacc[2 * j][2],     sacc[2 * j][3],     ph[j][1], plo[j][1]);
            split2(sacc[2 * j + 1][0], sacc[2 * j + 1][1], ph[j][2], plo[j][2]);
            split2(sacc[2 * j + 1][2], sacc[2 * j + 1][3], ph[j][3], plo[j][3]);
        }

        // ---- O += P V (3-term bf16 split, V^T via ldmatrix.trans) ----
        #pragma unroll
        for (int nd = 0; nd < 8; nd++) {
            #pragma unroll
            for (int j = 0; j < 4; j++) {
                uint32_t vb[2];
                uint32_t vo = (uint32_t)((j * 16 + (lane & 15)) * 144 + nd * 16);
                ldsm_x2_t(vb, sb + SVH + vo);
                mma_bf16(o[nd], ph[j],  vb);
                mma_bf16(o[nd], plo[j], vb);
                ldsm_x2_t(vb, sb + SVL + vo);
                mma_bf16(o[nd], ph[j],  vb);
            }
        }
    }

    // ---- finalize ----
    l0 += __shfl_xor_sync(0xffffffffu, l0, 1);
    l0 += __shfl_xor_sync(0xffffffffu, l0, 2);
    l1 += __shfl_xor_sync(0xffffffffu, l1, 1);
    l1 += __shfl_xor_sync(0xffffffffu, l1, 2);
    float inv0 = 1.0f / l0, inv1 = 1.0f / l1;
    int rowg = b * TT + qb * 128 + w * 16 + (lane >> 2);
    float* op = out + (size_t)rowg * CC + h * DD;
    #pragma unroll
    for (int nd = 0; nd < 8; nd++) {
        int col = nd * 8 + (lane & 3) * 2;
        *(float2*)(op + col)          = make_float2(o[nd][0] * inv0, o[nd][1] * inv0);
        *(float2*)(op + 8 * CC + col) = make_float2(o[nd][2] * inv1, o[nd][3] * inv1);
    }
}

// ---------------- per-row logsumexp + NLL ----------------
__global__ __launch_bounds__(256) void nll_k(const float* __restrict__ logits,
                                             const int* __restrict__ tgt,
                                             float* __restrict__ nll) {
    int row = blockIdx.x;
    const float* lp = logits + (size_t)row * VV;
    float m = -1e30f, s = 0.0f;
    for (int j = threadIdx.x; j < VV; j += 256) {
        float v = lp[j];
        float mn = fmaxf(m, v);
        s = s * __expf(m - mn) + __expf(v - mn);
        m = mn;
    }
    #pragma unroll
    for (int o = 16; o > 0; o >>= 1) {
        float m2 = __shfl_xor_sync(0xffffffffu, m, o);
        float s2 = __shfl_xor_sync(0xffffffffu, s, o);
        float mn = fmaxf(m, m2);
        s = s * __expf(m - mn) + s2 * __expf(m2 - mn);
        m = mn;
    }
    __shared__ float ms[8], ls[8];
    int wid = threadIdx.x >> 5;
    if ((threadIdx.x & 31) == 0) { ms[wid] = m; ls[wid] = s; }
    __syncthreads();
    if (threadIdx.x == 0) {
        float M = ms[0], S = ls[0];
        #pragma unroll
        for (int w = 1; w < 8; w++) {
            float mn = fmaxf(M, ms[w]);
            S = S * __expf(M - mn) + ls[w] * __expf(ms[w] - mn);
            M = mn;
        }
        float lse = M + logf(S);
        nll[row] = lse - lp[tgt[row]];
    }
}

__global__ __launch_bounds__(256) void loss_k(const float* __restrict__ nll,
                                              float* __restrict__ out_loss) {
    float s = 0.0f;
    for (int i = threadIdx.x; i < NROW; i += 256) s += nll[i];
    #pragma unroll
    for (int o = 16; o > 0; o >>= 1) s += __shfl_xor_sync(0xffffffffu, s, o);
    __shared__ float ws[8];
    int wid = threadIdx.x >> 5;
    if ((threadIdx.x & 31) == 0) ws[wid] = s;
    __syncthreads();
    if (threadIdx.x == 0) {
        float t = 0.0f;
        #pragma unroll
        for (int w = 0; w < 8; w++) t += ws[w];
        out_loss[0] = t / (float)NROW;
    }
}

// ---------------- orchestration ----------------
extern "C" void kernel_launch(void* const* d_in, const int* in_sizes, int n_in,
                              void* d_out, int out_size) {
    const int*   idx       = (const int*)  d_in[0];
    const int*   targets   = (const int*)  d_in[1];
    const float* tok_embed = (const float*)d_in[2];
    const float* pos_embed = (const float*)d_in[3];
    const float* qkv_w     = (const float*)d_in[4];
    const float* qkv_b     = (const float*)d_in[5];
    const float* out_w     = (const float*)d_in[6];
    const float* out_b     = (const float*)d_in[7];
    const float* ln1_w     = (const float*)d_in[8];
    const float* ln1_b     = (const float*)d_in[9];
    const float* ff1_w     = (const float*)d_in[10];
    const float* ff1_b     = (const float*)d_in[11];
    const float* ff2_w     = (const float*)d_in[12];
    const float* ff2_b     = (const float*)d_in[13];
    const float* ln2_w     = (const float*)d_in[14];
    const float* ln2_b     = (const float*)d_in[15];
    const float* lnf_w     = (const float*)d_in[16];
    const float* lnf_b     = (const float*)d_in[17];
    const float* head_w    = (const float*)d_in[18];
    const float* head_b    = (const float*)d_in[19];
    float* logits = (float*)d_out;

    static float *px = nullptr, *pxn = nullptr, *pqkv = nullptr,
                 *patt = nullptr, *pff = nullptr, *pnll = nullptr;
    if (!px) {
        cudaGetSymbolAddress((void**)&px,   g_x);
        cudaGetSymbolAddress((void**)&pxn,  g_xn);
        cudaGetSymbolAddress((void**)&pqkv, g_qkv);
        cudaGetSymbolAddress((void**)&patt, g_att);
        cudaGetSymbolAddress((void**)&pff,  g_ff);
        cudaGetSymbolAddress((void**)&pnll, g_nll);
        cudaFuncSetAttribute(attn_mma, cudaFuncAttributeMaxDynamicSharedMemorySize,
                             ATT_SMEM);
    }

    embed_k<<<NROW, 128>>>(idx, tok_embed, pos_embed, px);

    dim3 gQKV(NROW / 128, 3 * CC / 128);   // (32, 12)
    dim3 gPROJ(NROW / 128, CC / 128);      // (32, 4)
    dim3 gFF1(NROW / 128, 4 * CC / 128);   // (32, 16)
    dim3 gHEAD(NROW / 128, VV / 128);      // (32, 250)
    dim3 gATT(TT / 128, BBATCH * HH);      // (16, 16)

    for (int l = 0; l < LLAYERS; l++) {
        ln_k<<<NROW, 128>>>(px, ln1_w + l * CC, ln1_b + l * CC, pxn);
        gemm_mma<<<gQKV, 256>>>(pxn, qkv_w + (size_t)l * 3 * CC * CC,
                                qkv_b + (size_t)l * 3 * CC, nullptr,
                                pqkv, 3 * CC, CC, MODE_NONE);
        attn_mma<<<gATT, 256, ATT_SMEM>>>(pqkv, patt);
        gemm_mma<<<gPROJ, 256>>>(patt, out_w + (size_t)l * CC * CC,
                                 out_b + (size_t)l * CC, px,
                                 px, CC, CC, MODE_RES);
        ln_k<<<NROW, 128>>>(px, ln2_w + l * CC, ln2_b + l * CC, pxn);
        gemm_mma<<<gFF1, 256>>>(pxn, ff1_w + (size_t)l * 4 * CC * CC,
                                ff1_b + (size_t)l * 4 * CC, nullptr,
                                pff, 4 * CC, CC, MODE_GELU);
        gemm_mma<<<gPROJ, 256>>>(pff, ff2_w + (size_t)l * CC * 4 * CC,
                                 ff2_b + (size_t)l * CC, px,
                                 px, CC, 4 * CC, MODE_RES);
    }

    ln_k<<<NROW, 128>>>(px, lnf_w, lnf_b, pxn);
    gemm_mma<<<gHEAD, 256>>>(pxn, head_w, head_b, nullptr,
                             logits, VV, CC, MODE_NONE);

    nll_k<<<NROW, 256>>>(logits, targets, pnll);
    if (out_size > NROW * VV) {
        loss_k<<<1, 256>>>(pnll, logits + (size_t)NROW * VV);
    }
}

// round 5
// speedup vs baseline: 3.1271x; 1.2492x over previous
#include <cuda_runtime.h>
#include <cuda_bf16.h>
#include <math.h>
#include <stdint.h>

// Problem constants
#define CC 512
#define TT 2048
#define BBATCH 2
#define HH 8
#define DD 64
#define LLAYERS 6
#define VV 32000
#define NROW (BBATCH*TT)   // 4096

// weight plane offsets (bf16 elems)
#define OFF_QKV  0
#define OFF_OUT  4718592
#define OFF_FF1  6291456
#define OFF_FF2  12582912
#define OFF_HEAD 18874368
#define WTOTAL   35258368

// ---------------- scratch (no allocations allowed) ----------------
__device__ float g_x  [NROW * CC];
__device__ float g_nll[NROW];
__device__ __nv_bfloat16 g_wh[WTOTAL];
__device__ __nv_bfloat16 g_wl[WTOTAL];
__device__ __nv_bfloat16 g_xnh[NROW * CC],     g_xnl[NROW * CC];
__device__ __nv_bfloat16 g_qkvh[NROW * 3 * CC], g_qkvl[NROW * 3 * CC];
__device__ __nv_bfloat16 g_atth[NROW * CC],    g_attl[NROW * CC];
__device__ __nv_bfloat16 g_ffh[NROW * 4 * CC],  g_ffl[NROW * 4 * CC];

// ================= helpers =================
__device__ __forceinline__ uint32_t smem_u32(const void* p) {
    uint32_t a;
    asm("{ .reg .u64 t; cvta.to.shared.u64 t, %1; cvt.u32.u64 %0, t; }"
        : "=r"(a) : "l"(p));
    return a;
}
__device__ __forceinline__ void ldsm_x4(uint32_t* r, uint32_t addr) {
    asm volatile("ldmatrix.sync.aligned.m8n8.x4.shared.b16 {%0,%1,%2,%3}, [%4];"
                 : "=r"(r[0]), "=r"(r[1]), "=r"(r[2]), "=r"(r[3]) : "r"(addr));
}
__device__ __forceinline__ void ldsm_x2(uint32_t* r, uint32_t addr) {
    asm volatile("ldmatrix.sync.aligned.m8n8.x2.shared.b16 {%0,%1}, [%2];"
                 : "=r"(r[0]), "=r"(r[1]) : "r"(addr));
}
__device__ __forceinline__ void ldsm_x2_t(uint32_t* r, uint32_t addr) {
    asm volatile("ldmatrix.sync.aligned.m8n8.x2.trans.shared.b16 {%0,%1}, [%2];"
                 : "=r"(r[0]), "=r"(r[1]) : "r"(addr));
}
__device__ __forceinline__ void mma_bf16(float* c, const uint32_t* a, const uint32_t* b) {
    asm volatile("mma.sync.aligned.m16n8k16.row.col.f32.bf16.bf16.f32 "
                 "{%0,%1,%2,%3}, {%4,%5,%6,%7}, {%8,%9}, {%0,%1,%2,%3};"
                 : "+f"(c[0]), "+f"(c[1]), "+f"(c[2]), "+f"(c[3])
                 : "r"(a[0]), "r"(a[1]), "r"(a[2]), "r"(a[3]),
                   "r"(b[0]), "r"(b[1]));
}
__device__ __forceinline__ void split2(float a, float b, uint32_t& hi, uint32_t& lo) {
    __nv_bfloat16 ha = __float2bfloat16(a), hb = __float2bfloat16(b);
    __nv_bfloat16 la = __float2bfloat16(a - __bfloat162float(ha));
    __nv_bfloat16 lb = __float2bfloat16(b - __bfloat162float(hb));
    hi = (uint32_t)__bfloat16_as_ushort(ha) | ((uint32_t)__bfloat16_as_ushort(hb) << 16);
    lo = (uint32_t)__bfloat16_as_ushort(la) | ((uint32_t)__bfloat16_as_ushort(lb) << 16);
}
#define CP16(dst, src) \
    asm volatile("cp.async.cg.shared.global [%0], [%1], 16;" \
                 :: "r"(dst), "l"(src) : "memory")
#define CP_COMMIT() asm volatile("cp.async.commit_group;" ::: "memory")
#define CP_WAIT0()  asm volatile("cp.async.wait_group 0;" ::: "memory")

__device__ __forceinline__ float gelu_exact(float x) {
    return 0.5f * x * (1.0f + erff(x * 0.70710678118654752f));
}

// ---------------- weight split conversion ----------------
__global__ void cvtw_k(const float* __restrict__ s,
                       __nv_bfloat16* __restrict__ dh,
                       __nv_bfloat16* __restrict__ dl, int n4) {
    for (int i = blockIdx.x * blockDim.x + threadIdx.x; i < n4;
         i += gridDim.x * blockDim.x) {
        float4 v = ((const float4*)s)[i];
        uint32_t h0, l0, h1, l1;
        split2(v.x, v.y, h0, l0);
        split2(v.z, v.w, h1, l1);
        *(uint2*)(dh + (size_t)i * 4) = make_uint2(h0, h1);
        *(uint2*)(dl + (size_t)i * 4) = make_uint2(l0, l1);
    }
}

// ---------------- embedding ----------------
__global__ void embed_k(const int* __restrict__ idx,
                        const float* __restrict__ tok,
                        const float* __restrict__ pos,
                        float* __restrict__ x) {
    int row = blockIdx.x;
    int t   = row & (TT - 1);
    int tokid = idx[row];
    const float4* te = (const float4*)(tok + (size_t)tokid * CC);
    const float4* pe = (const float4*)(pos + (size_t)t * CC);
    float4* xr = (float4*)(x + (size_t)row * CC);
    for (int i = threadIdx.x; i < CC / 4; i += blockDim.x) {
        float4 a = te[i], b = pe[i];
        a.x += b.x; a.y += b.y; a.z += b.z; a.w += b.w;
        xr[i] = a;
    }
}

// ---------------- layernorm -> bf16 hi/lo planes ----------------
__global__ __launch_bounds__(128) void ln_bf(const float* __restrict__ x,
                                             const float* __restrict__ w,
                                             const float* __restrict__ b,
                                             __nv_bfloat16* __restrict__ yh,
                                             __nv_bfloat16* __restrict__ yl) {
    int row = blockIdx.x;
    int tid = threadIdx.x;
    const float4* xr = (const float4*)(x + (size_t)row * CC);
    float4 v = xr[tid];
    float s = v.x + v.y + v.z + v.w;
    float q = v.x * v.x + v.y * v.y + v.z * v.z + v.w * v.w;
    #pragma unroll
    for (int o = 16; o > 0; o >>= 1) {
        s += __shfl_xor_sync(0xffffffffu, s, o);
        q += __shfl_xor_sync(0xffffffffu, q, o);
    }
    __shared__ float ss[4], qq[4];
    int wid = tid >> 5;
    if ((tid & 31) == 0) { ss[wid] = s; qq[wid] = q; }
    __syncthreads();
    s = ss[0] + ss[1] + ss[2] + ss[3];
    q = qq[0] + qq[1] + qq[2] + qq[3];
    float mu   = s * (1.0f / CC);
    float var  = q * (1.0f / CC) - mu * mu;
    float rstd = rsqrtf(var + 1e-5f);
    float4 wv = ((const float4*)w)[tid];
    float4 bv = ((const float4*)b)[tid];
    float o0 = (v.x - mu) * rstd * wv.x + bv.x;
    float o1 = (v.y - mu) * rstd * wv.y + bv.y;
    float o2 = (v.z - mu) * rstd * wv.z + bv.z;
    float o3 = (v.w - mu) * rstd * wv.w + bv.w;
    uint32_t h0, l0, h1, l1;
    split2(o0, o1, h0, l0);
    split2(o2, o3, h1, l1);
    *(uint2*)(yh + (size_t)row * CC + tid * 4) = make_uint2(h0, h1);
    *(uint2*)(yl + (size_t)row * CC + tid * 4) = make_uint2(l0, l1);
}

// ================= bf16x3 MMA GEMM with cp.async, pre-split operands ======
#define MODE_NONE 0
#define MODE_GELU 1
#define MODE_RES  2
#define MODE_BF   3

#define BM 128
#define BN 128
#define BK 32
#define PLANE_B 10240          // 128 rows x 80 B
#define STAGE_B (4 * PLANE_B)  // Ah, Al, Bh, Bl
#define GEMM_SMEM (2 * STAGE_B)

__global__ __launch_bounds__(256, 2) void gemm_bf(
    const __nv_bfloat16* __restrict__ Ah, const __nv_bfloat16* __restrict__ Al,
    const __nv_bfloat16* __restrict__ Bh, const __nv_bfloat16* __restrict__ Bl,
    const float* __restrict__ bias, const float* __restrict__ res,
    float* __restrict__ Cf,
    __nv_bfloat16* __restrict__ Ch, __nv_bfloat16* __restrict__ Cl,
    int N, int K, int mode) {
    extern __shared__ __align__(16) char smem[];
    uint32_t sb = smem_u32(smem);

    int tid  = threadIdx.x;
    int lane = tid & 31;
    int wid  = tid >> 5;
    int wm   = wid & 1;
    int wn   = wid >> 1;
    int bm   = blockIdx.x * BM;
    int bn   = blockIdx.y * BN;

    // staging map: thread -> row r=tid>>1, two 16B chunks at cbase
    int r = tid >> 1;
    int cb = (tid & 1) * 2;                  // chunk index base (0 or 2)
    const __nv_bfloat16* Agp = Ah + (size_t)(bm + r) * K + cb * 8;
    const __nv_bfloat16* Alp = Al + (size_t)(bm + r) * K + cb * 8;
    const __nv_bfloat16* Bgp = Bh + (size_t)(bn + r) * K + cb * 8;
    const __nv_bfloat16* Blp = Bl + (size_t)(bn + r) * K + cb * 8;
    uint32_t sdst = (uint32_t)(r * 80 + cb * 16);

    float acc[4][4][4];
    #pragma unroll
    for (int i = 0; i < 4; i++)
        #pragma unroll
        for (int j = 0; j < 4; j++)
            #pragma unroll
            for (int k = 0; k < 4; k++) acc[i][j][k] = 0.0f;

    int nk = K / BK;

    // prologue: stage 0 into buf 0
    {
        uint32_t st = sb + sdst;
        CP16(st + 0 * PLANE_B,      Agp);     CP16(st + 0 * PLANE_B + 16, Agp + 8);
        CP16(st + 1 * PLANE_B,      Alp);     CP16(st + 1 * PLANE_B + 16, Alp + 8);
        CP16(st + 2 * PLANE_B,      Bgp);     CP16(st + 2 * PLANE_B + 16, Bgp + 8);
        CP16(st + 3 * PLANE_B,      Blp);     CP16(st + 3 * PLANE_B + 16, Blp + 8);
        CP_COMMIT();
    }

    for (int t = 0; t < nk; t++) {
        CP_WAIT0();
        __syncthreads();
        if (t + 1 < nk) {
            uint32_t st = sb + ((t + 1) & 1) * STAGE_B + sdst;
            const __nv_bfloat16* a0 = Agp + (t + 1) * BK;
            const __nv_bfloat16* a1 = Alp + (t + 1) * BK;
            const __nv_bfloat16* b0 = Bgp + (t + 1) * BK;
            const __nv_bfloat16* b1 = Blp + (t + 1) * BK;
            CP16(st + 0 * PLANE_B,      a0);  CP16(st + 0 * PLANE_B + 16, a0 + 8);
            CP16(st + 1 * PLANE_B,      a1);  CP16(st + 1 * PLANE_B + 16, a1 + 8);
            CP16(st + 2 * PLANE_B,      b0);  CP16(st + 2 * PLANE_B + 16, b0 + 8);
            CP16(st + 3 * PLANE_B,      b1);  CP16(st + 3 * PLANE_B + 16, b1 + 8);
        }
        CP_COMMIT();

        uint32_t cAh = sb + (t & 1) * STAGE_B;
        uint32_t cAl = cAh + PLANE_B;
        uint32_t cBh = cAh + 2 * PLANE_B;
        uint32_t cBl = cAh + 3 * PLANE_B;

        uint32_t ah[4][4], al[4][4], bh2[4][2], bl2[4][2];
        #pragma unroll
        for (int kf = 0; kf < 2; kf++) {
            uint32_t kb = kf * 32;
            uint32_t aoff = (uint32_t)((wm * 64 + (lane & 15)) * 80 + kb + ((lane >> 4) * 16));
            uint32_t boff = (uint32_t)((wn * 32 + (lane & 7)) * 80 + kb + (((lane >> 3) & 1) * 16));

            #pragma unroll
            for (int nf = 0; nf < 4; nf++) ldsm_x2(bh2[nf], cBh + boff + nf * 8 * 80);
            #pragma unroll
            for (int mf = 0; mf < 4; mf++) ldsm_x4(ah[mf], cAh + aoff + mf * 16 * 80);
            #pragma unroll
            for (int mf = 0; mf < 4; mf++)
                #pragma unroll
                for (int nf = 0; nf < 4; nf++)
                    mma_bf16(acc[mf][nf], ah[mf], bh2[nf]);

            #pragma unroll
            for (int mf = 0; mf < 4; mf++) ldsm_x4(al[mf], cAl + aoff + mf * 16 * 80);
            #pragma unroll
            for (int mf = 0; mf < 4; mf++)
                #pragma unroll
                for (int nf = 0; nf < 4; nf++)
                    mma_bf16(acc[mf][nf], al[mf], bh2[nf]);

            #pragma unroll
            for (int nf = 0; nf < 4; nf++) ldsm_x2(bl2[nf], cBl + boff + nf * 8 * 80);
            #pragma unroll
            for (int mf = 0; mf < 4; mf++)
                #pragma unroll
                for (int nf = 0; nf < 4; nf++)
                    mma_bf16(acc[mf][nf], ah[mf], bl2[nf]);
        }
    }

    // epilogue
    #pragma unroll
    for (int mf = 0; mf < 4; mf++) {
        int r0 = bm + wm * 64 + mf * 16 + (lane >> 2);
        #pragma unroll
        for (int nf = 0; nf < 4; nf++) {
            int col = bn + wn * 32 + nf * 8 + (lane & 3) * 2;
            float b0 = bias[col], b1 = bias[col + 1];
            float v0 = acc[mf][nf][0] + b0;
            float v1 = acc[mf][nf][1] + b1;
            float v2 = acc[mf][nf][2] + b0;
            float v3 = acc[mf][nf][3] + b1;
            if (mode == MODE_GELU) {
                v0 = gelu_exact(v0); v1 = gelu_exact(v1);
                v2 = gelu_exact(v2); v3 = gelu_exact(v3);
            } else if (mode == MODE_RES) {
                float2 r0v = *(const float2*)(res + (size_t)r0 * N + col);
                float2 r1v = *(const float2*)(res + (size_t)(r0 + 8) * N + col);
                v0 += r0v.x; v1 += r0v.y; v2 += r1v.x; v3 += r1v.y;
            }
            if (mode == MODE_RES || mode == MODE_NONE) {
                *(float2*)(Cf + (size_t)r0 * N + col)       = make_float2(v0, v1);
                *(float2*)(Cf + (size_t)(r0 + 8) * N + col) = make_float2(v2, v3);
            } else {
                uint32_t hp, lp;
                split2(v0, v1, hp, lp);
                *(uint32_t*)(Ch + (size_t)r0 * N + col) = hp;
                *(uint32_t*)(Cl + (size_t)r0 * N + col) = lp;
                split2(v2, v3, hp, lp);
                *(uint32_t*)(Ch + (size_t)(r0 + 8) * N + col) = hp;
                *(uint32_t*)(Cl + (size_t)(r0 + 8) * N + col) = lp;
            }
        }
    }
}

// ================= tensor-core flash attention (pre-split QKV planes) ========
// smem: QH 0..18432, QL ..36864; then 2 KV buffers of 36864 each
// (KH +0, KL +9216, VH +18432, VL +27648; pitch 144B, 64 rows)
#define SQH 0
#define SQL 18432
#define SKV 36864
#define KVB 36864
#define ATT_SMEM (SKV + 2 * KVB)   // 110592

__global__ __launch_bounds__(256) void attn_mma(
    const __nv_bfloat16* __restrict__ qkvh,
    const __nv_bfloat16* __restrict__ qkvl,
    __nv_bfloat16* __restrict__ outh,
    __nv_bfloat16* __restrict__ outl) {
    extern __shared__ __align__(16) char sm[];
    uint32_t sb = smem_u32(sm);
    int tid = threadIdx.x, lane = tid & 31, w = tid >> 5;
    int bh = blockIdx.y, b = bh >> 3, h = bh & 7;
    int qb = (int)gridDim.x - 1 - (int)blockIdx.x;   // heavy blocks first
    size_t bbase = (size_t)b * TT * (3 * CC);

    int ntiles = qb * 2 + 2;
    int sr2 = tid >> 2, qd = tid & 3;

    // prologue: issue KV tile 0 into buf 0
    {
        size_t ro = bbase + (size_t)sr2 * (3 * CC);
        const __nv_bfloat16* kh = qkvh + ro + CC + h * DD + qd * 16;
        const __nv_bfloat16* kl = qkvl + ro + CC + h * DD + qd * 16;
        const __nv_bfloat16* vh = qkvh + ro + 2 * CC + h * DD + qd * 16;
        const __nv_bfloat16* vl = qkvl + ro + 2 * CC + h * DD + qd * 16;
        uint32_t sd = sb + SKV + (uint32_t)(sr2 * 144 + qd * 32);
        CP16(sd + 0,         kh);  CP16(sd + 16,         kh + 8);
        CP16(sd + 9216,      kl);  CP16(sd + 9216 + 16,  kl + 8);
        CP16(sd + 18432,     vh);  CP16(sd + 18432 + 16, vh + 8);
        CP16(sd + 27648,     vl);  CP16(sd + 27648 + 16, vl + 8);
        CP_COMMIT();
    }

    // stage Q (copy bf16 planes)
    {
        int r = tid >> 1, hf = tid & 1;
        const __nv_bfloat16* qgh = qkvh + bbase + (size_t)(qb * 128 + r) * (3 * CC) + h * DD + hf * 32;
        const __nv_bfloat16* qgl = qkvl + bbase + (size_t)(qb * 128 + r) * (3 * CC) + h * DD + hf * 32;
        uint32_t qoff = (uint32_t)(r * 144 + hf * 64);
        #pragma unroll
        for (int j = 0; j < 4; j++) {
            *(uint4*)(sm + SQH + qoff + j * 16) = *(const uint4*)(qgh + j * 8);
            *(uint4*)(sm + SQL + qoff + j * 16) = *(const uint4*)(qgl + j * 8);
        }
    }
    __syncthreads();

    uint32_t qh[4][4], qlo[4][4];
    {
        uint32_t ro = (uint32_t)((w * 16 + (lane & 15)) * 144 + ((lane >> 4) * 16));
        #pragma unroll
        for (int kf = 0; kf < 4; kf++) {
            ldsm_x4(qh[kf],  sb + SQH + ro + kf * 32);
            ldsm_x4(qlo[kf], sb + SQL + ro + kf * 32);
        }
    }

    float o[8][4];
    #pragma unroll
    for (int i = 0; i < 8; i++)
        #pragma unroll
        for (int j = 0; j < 4; j++) o[i][j] = 0.0f;
    float m0 = -1e30f, m1 = -1e30f, l0 = 0.0f, l1 = 0.0f;

    for (int t = 0; t < ntiles; t++) {
        CP_WAIT0();
        __syncthreads();
        if (t + 1 < ntiles) {
            size_t ro = bbase + (size_t)((t + 1) * 64 + sr2) * (3 * CC);
            const __nv_bfloat16* kh = qkvh + ro + CC + h * DD + qd * 16;
            const __nv_bfloat16* kl = qkvl + ro + CC + h * DD + qd * 16;
            const __nv_bfloat16* vh = qkvh + ro + 2 * CC + h * DD + qd * 16;
            const __nv_bfloat16* vl = qkvl + ro + 2 * CC + h * DD + qd * 16;
            uint32_t sd = sb + SKV + ((t + 1) & 1) * KVB + (uint32_t)(sr2 * 144 + qd * 32);
            CP16(sd + 0,         kh);  CP16(sd + 16,         kh + 8);
            CP16(sd + 9216,      kl);  CP16(sd + 9216 + 16,  kl + 8);
            CP16(sd + 18432,     vh);  CP16(sd + 18432 + 16, vh + 8);
            CP16(sd + 27648,     vl);  CP16(sd + 27648 + 16, vl + 8);
        }
        CP_COMMIT();

        uint32_t KH = sb + SKV + (t & 1) * KVB;
        uint32_t KL = KH + 9216;
        uint32_t VH = KH + 18432;
        uint32_t VL = KH + 27648;

        // ---- S = Q K^T (3-term bf16 split) ----
        float sacc[8][4];
        #pragma unroll
        for (int i = 0; i < 8; i++)
            #pragma unroll
            for (int j = 0; j < 4; j++) sacc[i][j] = 0.0f;

        #pragma unroll
        for (int kf = 0; kf < 4; kf++) {
            uint32_t kb2[8][2];
            uint32_t bo = (uint32_t)((lane & 7) * 144 + kf * 32 + ((lane >> 3) & 1) * 16);
            #pragma unroll
            for (int nf = 0; nf < 8; nf++) ldsm_x2(kb2[nf], KH + bo + nf * 8 * 144);
            #pragma unroll
            for (int nf = 0; nf < 8; nf++) mma_bf16(sacc[nf], qh[kf],  kb2[nf]);
            #pragma unroll
            for (int nf = 0; nf < 8; nf++) mma_bf16(sacc[nf], qlo[kf], kb2[nf]);
            #pragma unroll
            for (int nf = 0; nf < 8; nf++) ldsm_x2(kb2[nf], KL + bo + nf * 8 * 144);
            #pragma unroll
            for (int nf = 0; nf < 8; nf++) mma_bf16(sacc[nf], qh[kf],  kb2[nf]);
        }
        // scale by 1/sqrt(D)=1/8 (exact power of two)
        #pragma unroll
        for (int nf = 0; nf < 8; nf++) {
            sacc[nf][0] *= 0.125f; sacc[nf][1] *= 0.125f;
            sacc[nf][2] *= 0.125f; sacc[nf][3] *= 0.125f;
        }

        // causal mask (diagonal tiles only)
        if (t >= 2 * qb) {
            int row0 = qb * 128 + w * 16 + (lane >> 2);
            int kc0  = t * 64 + (lane & 3) * 2;
            #pragma unroll
            for (int nf = 0; nf < 8; nf++) {
                int kc = kc0 + nf * 8;
                if (kc     > row0)     sacc[nf][0] = -1e30f;
                if (kc + 1 > row0)     sacc[nf][1] = -1e30f;
                if (kc     > row0 + 8) sacc[nf][2] = -1e30f;
                if (kc + 1 > row0 + 8) sacc[nf][3] = -1e30f;
            }
        }

        // online softmax
        float mx0 = -1e30f, mx1 = -1e30f;
        #pragma unroll
        for (int nf = 0; nf < 8; nf++) {
            mx0 = fmaxf(mx0, fmaxf(sacc[nf][0], sacc[nf][1]));
            mx1 = fmaxf(mx1, fmaxf(sacc[nf][2], sacc[nf][3]));
        }
        mx0 = fmaxf(mx0, __shfl_xor_sync(0xffffffffu, mx0, 1));
        mx0 = fmaxf(mx0, __shfl_xor_sync(0xffffffffu, mx0, 2));
        mx1 = fmaxf(mx1, __shfl_xor_sync(0xffffffffu, mx1, 1));
        mx1 = fmaxf(mx1, __shfl_xor_sync(0xffffffffu, mx1, 2));
        float mn0 = fmaxf(m0, mx0), mn1 = fmaxf(m1, mx1);
        float cs0 = __expf(m0 - mn0), cs1 = __expf(m1 - mn1);
        m0 = mn0; m1 = mn1;
        float ps0 = 0.0f, ps1 = 0.0f;
        #pragma unroll
        for (int nf = 0; nf < 8; nf++) {
            sacc[nf][0] = __expf(sacc[nf][0] - m0); ps0 += sacc[nf][0];
            sacc[nf][1] = __expf(sacc[nf][1] - m0); ps0 += sacc[nf][1];
            sacc[nf][2] = __expf(sacc[nf][2] - m1); ps1 += sacc[nf][2];
            sacc[nf][3] = __expf(sacc[nf][3] - m1); ps1 += sacc[nf][3];
        }
        l0 = l0 * cs0 + ps0;
        l1 = l1 * cs1 + ps1;
        #pragma unroll
        for (int nd = 0; nd < 8; nd++) {
            o[nd][0] *= cs0; o[nd][1] *= cs0;
            o[nd][2] *= cs1; o[nd][3] *= cs1;
        }

        // P fragments (hi/lo)
        uint32_t ph[4][4], plo[4][4];
        #pragma unroll
        for (int j = 0; j < 4; j++) {
            split2(sacc[2 * j][0],     sacc[2 * j][1],     ph[j][0], plo[j][0]);
            split2(sacc[2 * j][2],     sacc[2 * j][3],     ph[j][1], plo[j][1]);
            split2(sacc[2 * j + 1][0], sacc[2 * j + 1][1], ph[j][2], plo[j][2]);
            split2(sacc[2 * j + 1][2], sacc[2 * j + 1][3], ph[j][3], plo[j][3]);
        }

        // O += P V (3-term, V^T via ldmatrix.trans)
        #pragma unroll
        for (int nd = 0; nd < 8; nd++) {
            #pragma unroll
            for (int j = 0; j < 4; j++) {
                uint32_t vb[2];
                uint32_t vo = (uint32_t)((j * 16 + (lane & 15)) * 144 + nd * 16);
                ldsm_x2_t(vb, VH + vo);
                mma_bf16(o[nd], ph[j],  vb);
                mma_bf16(o[nd], plo[j], vb);
                ldsm_x2_t(vb, VL + vo);
                mma_bf16(o[nd], ph[j],  vb);
            }
        }
    }

    // finalize
    l0 += __shfl_xor_sync(0xffffffffu, l0, 1);
    l0 += __shfl_xor_sync(0xffffffffu, l0, 2);
    l1 += __shfl_xor_sync(0xffffffffu, l1, 1);
    l1 += __shfl_xor_sync(0xffffffffu, l1, 2);
    float inv0 = 1.0f / l0, inv1 = 1.0f / l1;
    int rowg = b * TT + qb * 128 + w * 16 + (lane >> 2);
    __nv_bfloat16* oph = outh + (size_t)rowg * CC + h * DD;
    __nv_bfloat16* opl = outl + (size_t)rowg * CC + h * DD;
    #pragma unroll
    for (int nd = 0; nd < 8; nd++) {
        int col = nd * 8 + (lane & 3) * 2;
        uint32_t hp, lp;
        split2(o[nd][0] * inv0, o[nd][1] * inv0, hp, lp);
        *(uint32_t*)(oph + col) = hp;
        *(uint32_t*)(opl + col) = lp;
        split2(o[nd][2] * inv1, o[nd][3] * inv1, hp, lp);
        *(uint32_t*)(oph + 8 * CC + col) = hp;
        *(uint32_t*)(opl + 8 * CC + col) = lp;
    }
}

// ---------------- per-row logsumexp + NLL ----------------
__global__ __launch_bounds__(256) void nll_k(const float* __restrict__ logits,
                                             const int* __restrict__ tgt,
                                             float* __restrict__ nll) {
    int row = blockIdx.x;
    const float* lp = logits + (size_t)row * VV;
    float m = -1e30f, s = 0.0f;
    for (int j = threadIdx.x; j < VV; j += 256) {
        float v = lp[j];
        float mn = fmaxf(m, v);
        s = s * __expf(m - mn) + __expf(v - mn);
        m = mn;
    }
    #pragma unroll
    for (int o = 16; o > 0; o >>= 1) {
        float m2 = __shfl_xor_sync(0xffffffffu, m, o);
        float s2 = __shfl_xor_sync(0xffffffffu, s, o);
        float mn = fmaxf(m, m2);
        s = s * __expf(m - mn) + s2 * __expf(m2 - mn);
        m = mn;
    }
    __shared__ float ms[8], ls[8];
    int wid = threadIdx.x >> 5;
    if ((threadIdx.x & 31) == 0) { ms[wid] = m; ls[wid] = s; }
    __syncthreads();
    if (threadIdx.x == 0) {
        float M = ms[0], S = ls[0];
        #pragma unroll
        for (int w = 1; w < 8; w++) {
            float mn = fmaxf(M, ms[w]);
            S = S * __expf(M - mn) + ls[w] * __expf(ms[w] - mn);
            M = mn;
        }
        float lse = M + logf(S);
        nll[row] = lse - lp[tgt[row]];
    }
}

__global__ __launch_bounds__(256) void loss_k(const float* __restrict__ nll,
                                              float* __restrict__ out_loss) {
    float s = 0.0f;
    for (int i = threadIdx.x; i < NROW; i += 256) s += nll[i];
    #pragma unroll
    for (int o = 16; o > 0; o >>= 1) s += __shfl_xor_sync(0xffffffffu, s, o);
    __shared__ float ws[8];
    int wid = threadIdx.x >> 5;
    if ((threadIdx.x & 31) == 0) ws[wid] = s;
    __syncthreads();
    if (threadIdx.x == 0) {
        float t = 0.0f;
        #pragma unroll
        for (int w = 0; w < 8; w++) t += ws[w];
        out_loss[0] = t / (float)NROW;
    }
}

// ---------------- orchestration ----------------
extern "C" void kernel_launch(void* const* d_in, const int* in_sizes, int n_in,
                              void* d_out, int out_size) {
    const int*   idx       = (const int*)  d_in[0];
    const int*   targets   = (const int*)  d_in[1];
    const float* tok_embed = (const float*)d_in[2];
    const float* pos_embed = (const float*)d_in[3];
    const float* qkv_w     = (const float*)d_in[4];
    const float* qkv_b     = (const float*)d_in[5];
    const float* out_w     = (const float*)d_in[6];
    const float* out_b     = (const float*)d_in[7];
    const float* ln1_w     = (const float*)d_in[8];
    const float* ln1_b     = (const float*)d_in[9];
    const float* ff1_w     = (const float*)d_in[10];
    const float* ff1_b     = (const float*)d_in[11];
    const float* ff2_w     = (const float*)d_in[12];
    const float* ff2_b     = (const float*)d_in[13];
    const float* ln2_w     = (const float*)d_in[14];
    const float* ln2_b     = (const float*)d_in[15];
    const float* lnf_w     = (const float*)d_in[16];
    const float* lnf_b     = (const float*)d_in[17];
    const float* head_w    = (const float*)d_in[18];
    const float* head_b    = (const float*)d_in[19];
    float* logits = (float*)d_out;

    static float *px = nullptr, *pnll = nullptr;
    static __nv_bfloat16 *wh, *wl, *xnh, *xnl, *qkvh, *qkvl, *atth, *attl, *ffh, *ffl;
    if (!px) {
        cudaGetSymbolAddress((void**)&px,   g_x);
        cudaGetSymbolAddress((void**)&pnll, g_nll);
        cudaGetSymbolAddress((void**)&wh,   g_wh);
        cudaGetSymbolAddress((void**)&wl,   g_wl);
        cudaGetSymbolAddress((void**)&xnh,  g_xnh);
        cudaGetSymbolAddress((void**)&xnl,  g_xnl);
        cudaGetSymbolAddress((void**)&qkvh, g_qkvh);
        cudaGetSymbolAddress((void**)&qkvl, g_qkvl);
        cudaGetSymbolAddress((void**)&atth, g_atth);
        cudaGetSymbolAddress((void**)&attl, g_attl);
        cudaGetSymbolAddress((void**)&ffh,  g_ffh);
        cudaGetSymbolAddress((void**)&ffl,  g_ffl);
        cudaFuncSetAttribute(gemm_bf,  cudaFuncAttributeMaxDynamicSharedMemorySize, GEMM_SMEM);
        cudaFuncSetAttribute(attn_mma, cudaFuncAttributeMaxDynamicSharedMemorySize, ATT_SMEM);
    }

    // weight split (per launch; graph-capturable, deterministic)
    cvtw_k<<<2048, 256>>>(qkv_w,  wh + OFF_QKV,  wl + OFF_QKV,  6 * 3 * CC * CC / 4);
    cvtw_k<<<2048, 256>>>(out_w,  wh + OFF_OUT,  wl + OFF_OUT,  6 * CC * CC / 4);
    cvtw_k<<<2048, 256>>>(ff1_w,  wh + OFF_FF1,  wl + OFF_FF1,  6 * 4 * CC * CC / 4);
    cvtw_k<<<2048, 256>>>(ff2_w,  wh + OFF_FF2,  wl + OFF_FF2,  6 * 4 * CC * CC / 4);
    cvtw_k<<<2048, 256>>>(head_w, wh + OFF_HEAD, wl + OFF_HEAD, VV * CC / 4);

    embed_k<<<NROW, 128>>>(idx, tok_embed, pos_embed, px);

    dim3 gQKV(NROW / 128, 3 * CC / 128);
    dim3 gPROJ(NROW / 128, CC / 128);
    dim3 gFF1(NROW / 128, 4 * CC / 128);
    dim3 gHEAD(NROW / 128, VV / 128);
    dim3 gATT(TT / 128, BBATCH * HH);

    for (int l = 0; l < LLAYERS; l++) {
        ln_bf<<<NROW, 128>>>(px, ln1_w + l * CC, ln1_b + l * CC, xnh, xnl);
        gemm_bf<<<gQKV, 256, GEMM_SMEM>>>(xnh, xnl,
            wh + OFF_QKV + (size_t)l * 3 * CC * CC, wl + OFF_QKV + (size_t)l * 3 * CC * CC,
            qkv_b + l * 3 * CC, nullptr, nullptr, qkvh, qkvl, 3 * CC, CC, MODE_BF);
        attn_mma<<<gATT, 256, ATT_SMEM>>>(qkvh, qkvl, atth, attl);
        gemm_bf<<<gPROJ, 256, GEMM_SMEM>>>(atth, attl,
            wh + OFF_OUT + (size_t)l * CC * CC, wl + OFF_OUT + (size_t)l * CC * CC,
            out_b + l * CC, px, px, nullptr, nullptr, CC, CC, MODE_RES);
        ln_bf<<<NROW, 128>>>(px, ln2_w + l * CC, ln2_b + l * CC, xnh, xnl);
        gemm_bf<<<gFF1, 256, GEMM_SMEM>>>(xnh, xnl,
            wh + OFF_FF1 + (size_t)l * 4 * CC * CC, wl + OFF_FF1 + (size_t)l * 4 * CC * CC,
            ff1_b + l * 4 * CC, nullptr, nullptr, ffh, ffl, 4 * CC, CC, MODE_GELU);
        gemm_bf<<<gPROJ, 256, GEMM_SMEM>>>(ffh, ffl,
            wh + OFF_FF2 + (size_t)l * CC * 4 * CC, wl + OFF_FF2 + (size_t)l * CC * 4 * CC,
            ff2_b + l * CC, px, px, nullptr, nullptr, CC, 4 * CC, MODE_RES);
    }

    ln_bf<<<NROW, 128>>>(px, lnf_w, lnf_b, xnh, xnl);
    gemm_bf<<<gHEAD, 256, GEMM_SMEM>>>(xnh, xnl,
        wh + OFF_HEAD, wl + OFF_HEAD,
        head_b, nullptr, logits, nullptr, nullptr, VV, CC, MODE_NONE);

    nll_k<<<NROW, 256>>>(logits, targets, pnll);
    if (out_size > NROW * VV) {
        loss_k<<<1, 256>>>(pnll, logits + (size_t)NROW * VV);
    }
}